// round 14
// baseline (speedup 1.0000x reference)
#include <cuda_runtime.h>
#include <cuda_fp16.h>
#include <math.h>
#include <stdint.h>

#define B_  8
#define H_  8
#define L_  1024
#define D_  64
#define DM_ 512
#define NC_ 5

// ---------------- scratch (__device__ globals; no allocation) ----------------
__device__ float g_G[B_*L_*15];        // G[bs][ll2][nc*3+t]
__device__ float g_q2[B_*L_*25];       // cluster_q2[bb][ll2][p*5+c]
__device__ float g_mu[B_*L_*NC_];      // mu[bb][ll2][j]
__device__ __half g_kh[B_*H_*L_*D_];   // KK split hi   [bh][key][dim]
__device__ __half g_kl[B_*H_*L_*D_];   // KK split lo
__device__ __half g_vh[B_*H_*D_*L_];   // V^T fp16 (hi) [bh][dim][key]
__device__ float g_lp_sum;
__device__ float g_ce_sum;

// ---------------- kernel 1 (MERGED): gmat (blocks 0..127) + vprep (128..639) -
__global__ void __launch_bounds__(512) k_prep(const float* __restrict__ K,
                                              const float* __restrict__ wk,
                                              const float* __restrict__ V) {
    __shared__ float sh[128*65];
    int blk = blockIdx.x;
    if (blk == 0 && threadIdx.x == 0) { g_lp_sum = 0.f; g_ce_sum = 0.f; }

    if (blk < 128) {
        int bs  = blk >> 4;
        int gg  = blk & 15;
        int q   = threadIdx.x & 63;
        int cg  = threadIdx.x >> 6;
        float (*red)[64][15] = (float(*)[64][15])sh;

        float acc[15];
        #pragma unroll
        for (int i = 0; i < 15; i++) acc[i] = 0.f;

        for (int c = cg*64; c < cg*64 + 64; c++) {
            int hh = c >> 6;
            int m  = c & 63;
            float kv = K[(((bs*H_ + hh)*L_) + m*16 + gg)*D_ + q];
            #pragma unroll
            for (int nc = 0; nc < 5; nc++)
                #pragma unroll
                for (int t = 0; t < 3; t++)
                    acc[nc*3+t] += kv * __ldg(&wk[nc*1536 + c*3 + t]);
        }

        #pragma unroll
        for (int i = 0; i < 15; i++) red[cg][q][i] = acc[i];
        __syncthreads();
        if (cg == 0) {
            int ll2 = gg*64 + q;
            #pragma unroll
            for (int i = 0; i < 15; i++) {
                float s = 0.f;
                #pragma unroll
                for (int r = 0; r < 8; r++) s += red[r][q][i];
                g_G[(bs*L_ + ll2)*15 + i] = s;
            }
        }
    } else {
        int vb = blk - 128;
        int bh = vb >> 3, ch = vb & 7;
        const float* Vb = V + ((size_t)bh*L_ + ch*128)*D_;
        float (*t)[65] = (float(*)[65])sh;
        for (int i = threadIdx.x; i < 128*64/4; i += 512) {
            float4 v4 = ((const float4*)Vb)[i];
            int r = i >> 4, cl = (i & 15)*4;
            t[r][cl] = v4.x; t[r][cl+1] = v4.y; t[r][cl+2] = v4.z; t[r][cl+3] = v4.w;
        }
        __syncthreads();
        for (int i = threadIdx.x; i < 64*128; i += 512) {
            int d = i >> 7, key = i & 127;
            g_vh[((size_t)bh*64 + d)*1024 + ch*128 + key] = __float2half_rn(t[key][d]);
        }
    }
}

// ---------------- kernel 2: per-(bb,ll2) cluster math + loss partials --------
__global__ void k_small(const float* __restrict__ bk,
                        const float* __restrict__ wck, const float* __restrict__ bck,
                        const float* __restrict__ wcq, const float* __restrict__ bcq) {
    int idx = blockIdx.x*blockDim.x + threadIdx.x;
    int bb = idx >> 10, ll = idx & 1023;

    float ckp[5][5];
    #pragma unroll
    for (int j = 0; j < 5; j++)
        #pragma unroll
        for (int nc = 0; nc < 5; nc++) {
            float a = bk[nc];
            #pragma unroll
            for (int t = 0; t < 3; t++) {
                int jj = j + t - 1;
                if (jj >= 0 && jj < 5) {
                    int bs = bb + jj - 4;
                    if (bs >= 1) a += g_G[(bs*L_ + ll)*15 + nc*3 + t];
                }
            }
            ckp[j][nc] = fmaxf(a, 0.f);
        }

    float ck[5][5], cq[5][5];
    float lp_local = 0.f;
    #pragma unroll
    for (int j = 0; j < 5; j++) {
        float zk[5], zq[5];
        #pragma unroll
        for (int o = 0; o < 5; o++) {
            float sk = bck[o], sq = bcq[o];
            #pragma unroll
            for (int nc = 0; nc < 5; nc++) {
                sk += ckp[j][nc]*wck[o*5+nc];
                sq += ckp[j][nc]*wcq[o*5+nc];
            }
            zk[o] = sk; zq[o] = sq;
        }
        float mk = zk[0], mq = zq[0];
        #pragma unroll
        for (int o = 1; o < 5; o++) { mk = fmaxf(mk, zk[o]); mq = fmaxf(mq, zq[o]); }
        float sks = 0.f, sqs = 0.f;
        #pragma unroll
        for (int o = 0; o < 5; o++) {
            float ek = expf(zk[o]-mk), eq = expf(zq[o]-mq);
            ck[j][o] = ek; cq[j][o] = eq; sks += ek; sqs += eq;
        }
        float ik = 1.f/sks, iq = 1.f/sqs;
        #pragma unroll
        for (int o = 0; o < 5; o++) { ck[j][o] *= ik; cq[j][o] *= iq; }

        float mu = 0.f, x = 0.f;
        #pragma unroll
        for (int o = 0; o < 5; o++) { mu += cq[j][o]; x += ck[j][o]; }
        mu *= 0.2f; x *= 0.2f;
        float var = 0.f;
        #pragma unroll
        for (int o = 0; o < 5; o++) { float d = cq[j][o]-mu; var += d*d; }
        var *= 0.25f;
        float sd    = sqrtf(var);
        float sigma = logf(1.f + expf(sd));
        float z     = (x - mu)/sigma;
        lp_local += -0.5f*z*z - logf(sigma) - 0.91893853320467274f;
        g_mu[idx*5 + j] = mu;
    }

    #pragma unroll
    for (int p = 0; p < 5; p++) {
        float sc[5];
        #pragma unroll
        for (int j = 0; j < 5; j++) {
            if (j > p) { sc[j] = -1e9f; continue; }
            float d = 0.f;
            #pragma unroll
            for (int c = 0; c < 5; c++) d += cq[p][c]*ck[j][c];
            sc[j] = d*0.2f;
        }
        float mx = sc[0];
        #pragma unroll
        for (int j = 1; j < 5; j++) mx = fmaxf(mx, sc[j]);
        float se = 0.f, ew[5];
        #pragma unroll
        for (int j = 0; j < 5; j++) { ew[j] = expf(sc[j]-mx); se += ew[j]; }
        float inv = 1.f/se;
        #pragma unroll
        for (int c = 0; c < 5; c++) {
            float v = 0.f;
            #pragma unroll
            for (int j = 0; j < 5; j++) v += ew[j]*cq[j][c];
            g_q2[idx*25 + p*5 + c] = v*inv;
        }
    }

    #pragma unroll
    for (int off = 16; off; off >>= 1)
        lp_local += __shfl_down_sync(0xffffffff, lp_local, off);
    if ((threadIdx.x & 31) == 0) atomicAdd(&g_lp_sum, lp_local);
}

// ---------------- kernel 3: warp-cooperative fused conv_back + u2-sum --------
__global__ void __launch_bounds__(1024) k_proj(const float* __restrict__ wpb,
                                               const float* __restrict__ bpb) {
    extern __shared__ float smp[];
    float* q2s = smp;            // 1024 rows x 28
    float* wsh = smp + 28672;    // 512 rows x 16
    int blk = blockIdx.x;
    int qtr = blk & 3;
    int hh  = (blk >> 2) & 7;
    int bb  = blk >> 5;

    const float* q2b = g_q2 + (bb << 10)*25;
    for (int i = threadIdx.x; i < 25600; i += 1024) {
        int row = i / 25;
        int col = i - row*25;
        q2s[row*28 + col] = q2b[i];
    }
    for (int i = threadIdx.x; i < 512*16; i += 1024) {
        int c = i >> 4, e = i & 15;
        wsh[i] = (e < 15) ? __ldg(&wpb[c*15 + e]) : __ldg(&bpb[c]);
    }
    __syncthreads();

    int p0 = qtr*3277;
    int p1 = min(p0 + 3277, 13108);
    size_t obase = (size_t)(bb*8 + hh)*65536;
    int warp = threadIdx.x >> 5, lane = threadIdx.x & 31;

    for (int kb = p0 + warp*31; kb < p1; kb += 32*31) {
        int k = kb + lane;
        float acc[5] = {0.f, 0.f, 0.f, 0.f, 0.f};

        #pragma unroll
        for (int u2 = 0; u2 < 5; u2++) {
            int kw = min(kb + lane, 13107);
            int W  = (hh*5 + u2)*13107 + hh + kw;
            int c  = W >> 10, ll = W & 1023;

            const float4* qp = (const float4*)(q2s + ll*28);
            float4 q0 = qp[0], q1 = qp[1], q2v = qp[2],
                   q3 = qp[3], q4 = qp[4], q5 = qp[5];
            float q24 = q2s[ll*28 + 24];
            const float4* wp = (const float4*)(wsh + c*16);
            float4 w0 = wp[0], w1 = wp[1], w2 = wp[2], w3 = wp[3];

            float qr[25] = {q0.x,q0.y,q0.z,q0.w, q1.x,q1.y,q1.z,q1.w,
                            q2v.x,q2v.y,q2v.z,q2v.w, q3.x,q3.y,q3.z,q3.w,
                            q4.x,q4.y,q4.z,q4.w, q5.x,q5.y,q5.z,q5.w, q24};
            float wr[15] = {w0.x,w0.y,w0.z,w0.w, w1.x,w1.y,w1.z,w1.w,
                            w2.x,w2.y,w2.z,w2.w, w3.x,w3.y,w3.z};
            float bias = w3.w;

            float Dm[5][3];
            #pragma unroll
            for (int jj = 0; jj < 5; jj++)
                #pragma unroll
                for (int t = 0; t < 3; t++) {
                    float d = 0.f;
                    #pragma unroll
                    for (int nc = 0; nc < 5; nc++)
                        d += qr[jj*5 + nc]*wr[nc*3 + t];
                    Dm[jj][t] = d;
                }
            float y[5];
            #pragma unroll
            for (int j = 0; j < 5; j++) {
                float v = bias + Dm[j][1];
                if (j >= 1) v += Dm[j-1][0];
                if (j <= 3) v += Dm[j+1][2];
                y[j] = fmaxf(v, 0.f);
            }

            float ynx[5];
            #pragma unroll
            for (int j = 0; j < 5; j++)
                ynx[j] = __shfl_down_sync(0xffffffffu, y[j], 1);

            #pragma unroll
            for (int i = 0; i < 5; i++)
                acc[i] += (u2 + i < 5) ? y[u2 + i] : ynx[i - 5 + u2];
        }

        if (lane < 31 && k < p1) {
            int pos0 = k*5;
            int valid = min(5, 65536 - pos0);
            #pragma unroll
            for (int i = 0; i < 5; i++)
                if (i < valid) {
                    __half h = __float2half_rn(acc[i]);
                    g_kh[obase + pos0 + i] = h;
                    g_kl[obase + pos0 + i] = __float2half_rn(acc[i] - __half2float(h));
                }
        }
    }
}

// ---------------- kernel 5: CE term ------------------------------------------
__global__ void k_ce() {
    int bb = blockIdx.x / 5, j = blockIdx.x % 5;
    const float* base = g_mu + (bb << 10)*5 + j;
    __shared__ float sh[256];
    int tid = threadIdx.x;

    float mx = -1e30f;
    for (int ll = tid; ll < L_; ll += 256) mx = fmaxf(mx, base[ll*5]);
    sh[tid] = mx; __syncthreads();
    for (int s = 128; s > 0; s >>= 1) { if (tid < s) sh[tid] = fmaxf(sh[tid], sh[tid+s]); __syncthreads(); }
    mx = sh[0]; __syncthreads();

    float se = 0.f;
    for (int ll = tid; ll < L_; ll += 256) se += expf(base[ll*5] - mx);
    sh[tid] = se; __syncthreads();
    for (int s = 128; s > 0; s >>= 1) { if (tid < s) sh[tid] += sh[tid+s]; __syncthreads(); }
    float lse = mx + logf(sh[0]); __syncthreads();

    float acc = 0.f;
    for (int ll = tid; ll < L_; ll += 256) { float m = base[ll*5]; acc += m*(m - lse); }
    sh[tid] = acc; __syncthreads();
    for (int s = 128; s > 0; s >>= 1) { if (tid < s) sh[tid] += sh[tid+s]; __syncthreads(); }
    if (tid == 0) atomicAdd(&g_ce_sum, sh[0]);
}

__global__ void k_loss(float* out, int n) {
    out[n] = -(g_lp_sum / 40960.f) - (g_ce_sum / 40.f);
}

// ---------------- kernel 4: flash attention, hf-fused QK for ILP -------------
__device__ __forceinline__ void mma16816(float d[4], const uint32_t a[4], const uint32_t b0, const uint32_t b1) {
    asm volatile("mma.sync.aligned.m16n8k16.row.col.f32.f16.f16.f32 "
                 "{%0,%1,%2,%3}, {%4,%5,%6,%7}, {%8,%9}, {%0,%1,%2,%3};\n"
                 : "+f"(d[0]), "+f"(d[1]), "+f"(d[2]), "+f"(d[3])
                 : "r"(a[0]), "r"(a[1]), "r"(a[2]), "r"(a[3]), "r"(b0), "r"(b1));
}
__device__ __forceinline__ void ldm4(uint32_t r[4], uint32_t addr) {
    asm volatile("ldmatrix.sync.aligned.m8n8.x4.shared.b16 {%0,%1,%2,%3}, [%4];\n"
                 : "=r"(r[0]), "=r"(r[1]), "=r"(r[2]), "=r"(r[3]) : "r"(addr));
}
__device__ __forceinline__ uint32_t packh(__half x, __half y) {
    __half2 h = __halves2half2(x, y);
    return *reinterpret_cast<uint32_t*>(&h);
}
__device__ __forceinline__ void split2(float2 f, uint32_t& hi, uint32_t& lo) {
    __half hx = __float2half_rn(f.x), hy = __float2half_rn(f.y);
    __half lx = __float2half_rn(f.x - __half2float(hx));
    __half ly = __float2half_rn(f.y - __half2float(hy));
    hi = packh(hx, hy); lo = packh(lx, ly);
}
__device__ __forceinline__ float ex2(float x) {
    float y; asm("ex2.approx.f32 %0, %1;" : "=f"(y) : "f"(x)); return y;
}
__device__ __forceinline__ void cpasync16(uint32_t smem_addr, const void* gptr) {
    asm volatile("cp.async.cg.shared.global [%0], [%1], 16;\n" :: "r"(smem_addr), "l"(gptr));
}

#define PADT 72
#define TILE_H (64*PADT)
#define STAGE_B (3*TILE_H*2)

__global__ void __launch_bounds__(256, 2) k_attn(const float* __restrict__ Q,
                                                 float* __restrict__ out) {
    extern __shared__ __half sm[];
    int bh = blockIdx.x >> 3, qt = blockIdx.x & 7;
    int tid = threadIdx.x, w = tid >> 5, lane = tid & 31;
    int g = lane >> 2, c4 = lane & 3;

    const __half* khg = g_kh + (size_t)bh*L_*D_;
    const __half* klg = g_kl + (size_t)bh*L_*D_;
    const __half* vhg = g_vh + (size_t)bh*D_*L_;

    const float LOG2E = 1.44269504088896340736f;
    uint32_t qfh[4][4], qfl[4][4];
    const float* Qb = Q + ((size_t)bh*L_ + qt*128 + w*16)*D_;
    #pragma unroll
    for (int kc = 0; kc < 4; kc++) {
        int col0 = kc*16 + 2*c4;
        float2 a0 = *(const float2*)(Qb + g*D_     + col0);
        float2 a1 = *(const float2*)(Qb + (g+8)*D_ + col0);
        float2 a2 = *(const float2*)(Qb + g*D_     + col0 + 8);
        float2 a3 = *(const float2*)(Qb + (g+8)*D_ + col0 + 8);
        a0.x *= LOG2E; a0.y *= LOG2E; a1.x *= LOG2E; a1.y *= LOG2E;
        a2.x *= LOG2E; a2.y *= LOG2E; a3.x *= LOG2E; a3.y *= LOG2E;
        split2(a0, qfh[kc][0], qfl[kc][0]);
        split2(a1, qfh[kc][1], qfl[kc][1]);
        split2(a2, qfh[kc][2], qfl[kc][2]);
        split2(a3, qfh[kc][3], qfl[kc][3]);
    }

    float o[8][4];
    #pragma unroll
    for (int i = 0; i < 8; i++)
        #pragma unroll
        for (int e = 0; e < 4; e++) o[i][e] = 0.f;
    float m0 = -1e30f, m1 = -1e30f, l0 = 0.f, l1 = 0.f;

    uint32_t smbase = (uint32_t)__cvta_generic_to_shared(sm);
    int lrow = ((lane >> 4) << 3) + (lane & 7);
    uint32_t lsel = ((lane >> 3) & 1) << 3;
    uint32_t laneoff = (uint32_t)(lrow*PADT + lsel)*2;

    auto stage = [&](int kt, int s) {
        uint32_t b = smbase + (uint32_t)s*STAGE_B;
        #pragma unroll
        for (int i = tid; i < 1536; i += 256) {
            int arr = i >> 9, j = i & 511;
            int r = j >> 3, ch = j & 7;
            const __half* src;
            if (arr == 0)      src = khg + kt*4096 + r*64 + ch*8;
            else if (arr == 1) src = klg + kt*4096 + r*64 + ch*8;
            else               src = vhg + r*1024 + kt*64 + ch*8;
            cpasync16(b + (uint32_t)arr*(TILE_H*2) + (uint32_t)(r*PADT + ch*8)*2, src);
        }
    };

    stage(0, 0);
    asm volatile("cp.async.commit_group;\n");
    stage(1, 1);
    asm volatile("cp.async.commit_group;\n");

    int bufA = 0, bufB = 1, bufC = 2;
    for (int kt = 0; kt < 16; kt++) {
        asm volatile("cp.async.wait_group 1;\n");
        __syncthreads();

        // prefetch kt+2 FIRST so cp.async overlaps the whole compute body
        if (kt < 14) stage(kt+2, bufC);
        asm volatile("cp.async.commit_group;\n");

        uint32_t kh_b = smbase + (uint32_t)bufA*STAGE_B + laneoff;
        uint32_t kl_b = kh_b + TILE_H*2;
        uint32_t vh_b = kl_b + TILE_H*2;

        // ---- QK for BOTH 32-key halves: 96 independent HMMAs ----
        float s[2][4][4];
        #pragma unroll
        for (int hf = 0; hf < 2; hf++)
            #pragma unroll
            for (int nt = 0; nt < 4; nt++)
                #pragma unroll
                for (int e = 0; e < 4; e++) s[hf][nt][e] = 0.f;

        #pragma unroll
        for (int hf = 0; hf < 2; hf++)
            #pragma unroll
            for (int kc = 0; kc < 4; kc++)
                #pragma unroll
                for (int np = 0; np < 2; np++) {
                    uint32_t off = (uint32_t)((hf*32 + np*16)*PADT + kc*16)*2;
                    uint32_t bhm[4], blm[4];
                    ldm4(bhm, kh_b + off);
                    ldm4(blm, kl_b + off);
                    mma16816(s[hf][np*2],   qfh[kc], bhm[0], bhm[1]);
                    mma16816(s[hf][np*2],   qfl[kc], bhm[0], bhm[1]);
                    mma16816(s[hf][np*2],   qfh[kc], blm[0], blm[1]);
                    mma16816(s[hf][np*2+1], qfh[kc], bhm[2], bhm[3]);
                    mma16816(s[hf][np*2+1], qfl[kc], bhm[2], bhm[3]);
                    mma16816(s[hf][np*2+1], qfh[kc], blm[2], blm[3]);
                }

        // ---- softmax + PV per half ----
        #pragma unroll
        for (int hf = 0; hf < 2; hf++) {
            float mt0 = s[hf][0][0], mt1 = s[hf][0][2];
            #pragma unroll
            for (int nt = 0; nt < 4; nt++) {
                mt0 = fmaxf(mt0, fmaxf(s[hf][nt][0], s[hf][nt][1]));
                mt1 = fmaxf(mt1, fmaxf(s[hf][nt][2], s[hf][nt][3]));
            }
            mt0 = fmaxf(mt0, __shfl_xor_sync(0xffffffff, mt0, 1));
            mt0 = fmaxf(mt0, __shfl_xor_sync(0xffffffff, mt0, 2));
            mt1 = fmaxf(mt1, __shfl_xor_sync(0xffffffff, mt1, 1));
            mt1 = fmaxf(mt1, __shfl_xor_sync(0xffffffff, mt1, 2));
            float m0n = fmaxf(m0, mt0), m1n = fmaxf(m1, mt1);
            bool need = (m0n > m0) || (m1n > m1);
            if (__ballot_sync(0xffffffffu, need)) {
                float sc0 = ex2(m0 - m0n), sc1 = ex2(m1 - m1n);
                l0 *= sc0; l1 *= sc1;
                #pragma unroll
                for (int i = 0; i < 8; i++) {
                    o[i][0] *= sc0; o[i][1] *= sc0;
                    o[i][2] *= sc1; o[i][3] *= sc1;
                }
            }
            m0 = m0n; m1 = m1n;

            uint32_t PH[4][2];
            #pragma unroll
            for (int nt = 0; nt < 4; nt++) {
                float p0 = ex2(s[hf][nt][0] - m0), p1 = ex2(s[hf][nt][1] - m0);
                float p2 = ex2(s[hf][nt][2] - m1), p3 = ex2(s[hf][nt][3] - m1);
                l0 += p0 + p1; l1 += p2 + p3;
                PH[nt][0] = packh(__float2half_rn(p0), __float2half_rn(p1));
                PH[nt][1] = packh(__float2half_rn(p2), __float2half_rn(p3));
            }

            #pragma unroll
            for (int kc2 = 0; kc2 < 2; kc2++) {
                uint32_t Ah[4] = {PH[2*kc2][0], PH[2*kc2][1], PH[2*kc2+1][0], PH[2*kc2+1][1]};
                #pragma unroll
                for (int np = 0; np < 4; np++) {
                    uint32_t off = (uint32_t)(np*16*PADT + hf*32 + kc2*16)*2;
                    uint32_t bvm[4];
                    ldm4(bvm, vh_b + off);
                    mma16816(o[np*2],   Ah, bvm[0], bvm[1]);
                    mma16816(o[np*2+1], Ah, bvm[2], bvm[3]);
                }
            }
        }

        int tmp = bufA; bufA = bufB; bufB = bufC; bufC = tmp;
    }

    l0 += __shfl_xor_sync(0xffffffff, l0, 1);
    l0 += __shfl_xor_sync(0xffffffff, l0, 2);
    l1 += __shfl_xor_sync(0xffffffff, l1, 1);
    l1 += __shfl_xor_sync(0xffffffff, l1, 2);
    float inv0 = 1.f/l0, inv1 = 1.f/l1;

    float* Ob = out + ((size_t)bh*L_ + qt*128 + w*16)*D_;
    #pragma unroll
    for (int nt = 0; nt < 8; nt++) {
        int col = nt*8 + 2*c4;
        *(float2*)(Ob + g*D_     + col) = make_float2(o[nt][0]*inv0, o[nt][1]*inv0);
        *(float2*)(Ob + (g+8)*D_ + col) = make_float2(o[nt][2]*inv1, o[nt][3]*inv1);
    }
}

// ---------------- launcher ---------------------------------------------------
extern "C" void kernel_launch(void* const* d_in, const int* in_sizes, int n_in,
                              void* d_out, int out_size) {
    const float* Q   = (const float*)d_in[0];
    const float* K   = (const float*)d_in[1];
    const float* V   = (const float*)d_in[2];
    const float* wpk = (const float*)d_in[3];
    const float* bpk = (const float*)d_in[4];
    const float* wpb = (const float*)d_in[5];
    const float* bpb = (const float*)d_in[6];
    const float* wck = (const float*)d_in[7];
    const float* bck = (const float*)d_in[8];
    const float* wcq = (const float*)d_in[9];
    const float* bcq = (const float*)d_in[10];
    float* out = (float*)d_out;

    const int ATTN_SMEM = 3*STAGE_B;                 // 82944 B
    const int PROJ_SMEM = (1024*28 + 512*16)*4;      // 147456 B
    cudaFuncSetAttribute(k_attn, cudaFuncAttributeMaxDynamicSharedMemorySize, ATTN_SMEM);
    cudaFuncSetAttribute(k_proj, cudaFuncAttributeMaxDynamicSharedMemorySize, PROJ_SMEM);

    k_prep<<<128 + B_*H_*8, 512>>>(K, wpk, V);            // 1
    k_small<<<(B_*L_)/64, 64>>>(bpk, wck, bck, wcq, bcq); // 2
    k_proj<<<B_*H_*4, 1024, PROJ_SMEM>>>(wpb, bpb);       // 3
    k_attn<<<B_*H_*8, 256, ATTN_SMEM>>>(Q, out);          // 4  <- ncu captures this
    k_ce<<<B_*NC_, 256>>>();                              // 5
    const int N = B_*H_*L_*D_;
    if (out_size > N) k_loss<<<1, 1>>>(out, N);           // 6
}

// round 15
// speedup vs baseline: 1.0109x; 1.0109x over previous
#include <cuda_runtime.h>
#include <cuda_fp16.h>
#include <math.h>
#include <stdint.h>

#define B_  8
#define H_  8
#define L_  1024
#define D_  64
#define DM_ 512
#define NC_ 5

// ---------------- scratch (__device__ globals; no allocation) ----------------
__device__ float g_G[B_*L_*15];        // G[bs][ll2][nc*3+t]
__device__ float g_q2[B_*L_*25];       // cluster_q2[bb][ll2][p*5+c]
__device__ float g_mu[B_*L_*NC_];      // mu[bb][ll2][j]
__device__ __half g_kh[B_*H_*L_*D_];   // KK split hi   [bh][key][dim]
__device__ __half g_kl[B_*H_*L_*D_];   // KK split lo
__device__ __half g_vh[B_*H_*D_*L_];   // V^T fp16 (hi) [bh][dim][key]
__device__ float g_lp_sum;
__device__ float g_ce_sum;

// ---------------- kernel 1 (MERGED): gmat (blocks 0..127) + vprep (128..639) -
__global__ void __launch_bounds__(512) k_prep(const float* __restrict__ K,
                                              const float* __restrict__ wk,
                                              const float* __restrict__ V) {
    __shared__ float sh[128*65];
    int blk = blockIdx.x;
    if (blk == 0 && threadIdx.x == 0) { g_lp_sum = 0.f; g_ce_sum = 0.f; }

    if (blk < 128) {
        int bs  = blk >> 4;
        int gg  = blk & 15;
        int q   = threadIdx.x & 63;
        int cg  = threadIdx.x >> 6;
        float (*red)[64][15] = (float(*)[64][15])sh;

        float acc[15];
        #pragma unroll
        for (int i = 0; i < 15; i++) acc[i] = 0.f;

        for (int c = cg*64; c < cg*64 + 64; c++) {
            int hh = c >> 6;
            int m  = c & 63;
            float kv = K[(((bs*H_ + hh)*L_) + m*16 + gg)*D_ + q];
            #pragma unroll
            for (int nc = 0; nc < 5; nc++)
                #pragma unroll
                for (int t = 0; t < 3; t++)
                    acc[nc*3+t] += kv * __ldg(&wk[nc*1536 + c*3 + t]);
        }

        #pragma unroll
        for (int i = 0; i < 15; i++) red[cg][q][i] = acc[i];
        __syncthreads();
        if (cg == 0) {
            int ll2 = gg*64 + q;
            #pragma unroll
            for (int i = 0; i < 15; i++) {
                float s = 0.f;
                #pragma unroll
                for (int r = 0; r < 8; r++) s += red[r][q][i];
                g_G[(bs*L_ + ll2)*15 + i] = s;
            }
        }
    } else {
        int vb = blk - 128;
        int bh = vb >> 3, ch = vb & 7;
        const float* Vb = V + ((size_t)bh*L_ + ch*128)*D_;
        float (*t)[65] = (float(*)[65])sh;
        for (int i = threadIdx.x; i < 128*64/4; i += 512) {
            float4 v4 = ((const float4*)Vb)[i];
            int r = i >> 4, cl = (i & 15)*4;
            t[r][cl] = v4.x; t[r][cl+1] = v4.y; t[r][cl+2] = v4.z; t[r][cl+3] = v4.w;
        }
        __syncthreads();
        for (int i = threadIdx.x; i < 64*128; i += 512) {
            int d = i >> 7, key = i & 127;
            g_vh[((size_t)bh*64 + d)*1024 + ch*128 + key] = __float2half_rn(t[key][d]);
        }
    }
}

// ---------------- kernel 2: per-(bb,ll2) cluster math + loss partials --------
__global__ void k_small(const float* __restrict__ bk,
                        const float* __restrict__ wck, const float* __restrict__ bck,
                        const float* __restrict__ wcq, const float* __restrict__ bcq) {
    int idx = blockIdx.x*blockDim.x + threadIdx.x;
    int bb = idx >> 10, ll = idx & 1023;

    float ckp[5][5];
    #pragma unroll
    for (int j = 0; j < 5; j++)
        #pragma unroll
        for (int nc = 0; nc < 5; nc++) {
            float a = bk[nc];
            #pragma unroll
            for (int t = 0; t < 3; t++) {
                int jj = j + t - 1;
                if (jj >= 0 && jj < 5) {
                    int bs = bb + jj - 4;
                    if (bs >= 1) a += g_G[(bs*L_ + ll)*15 + nc*3 + t];
                }
            }
            ckp[j][nc] = fmaxf(a, 0.f);
        }

    float ck[5][5], cq[5][5];
    float lp_local = 0.f;
    #pragma unroll
    for (int j = 0; j < 5; j++) {
        float zk[5], zq[5];
        #pragma unroll
        for (int o = 0; o < 5; o++) {
            float sk = bck[o], sq = bcq[o];
            #pragma unroll
            for (int nc = 0; nc < 5; nc++) {
                sk += ckp[j][nc]*wck[o*5+nc];
                sq += ckp[j][nc]*wcq[o*5+nc];
            }
            zk[o] = sk; zq[o] = sq;
        }
        float mk = zk[0], mq = zq[0];
        #pragma unroll
        for (int o = 1; o < 5; o++) { mk = fmaxf(mk, zk[o]); mq = fmaxf(mq, zq[o]); }
        float sks = 0.f, sqs = 0.f;
        #pragma unroll
        for (int o = 0; o < 5; o++) {
            float ek = expf(zk[o]-mk), eq = expf(zq[o]-mq);
            ck[j][o] = ek; cq[j][o] = eq; sks += ek; sqs += eq;
        }
        float ik = 1.f/sks, iq = 1.f/sqs;
        #pragma unroll
        for (int o = 0; o < 5; o++) { ck[j][o] *= ik; cq[j][o] *= iq; }

        float mu = 0.f, x = 0.f;
        #pragma unroll
        for (int o = 0; o < 5; o++) { mu += cq[j][o]; x += ck[j][o]; }
        mu *= 0.2f; x *= 0.2f;
        float var = 0.f;
        #pragma unroll
        for (int o = 0; o < 5; o++) { float d = cq[j][o]-mu; var += d*d; }
        var *= 0.25f;
        float sd    = sqrtf(var);
        float sigma = logf(1.f + expf(sd));
        float z     = (x - mu)/sigma;
        lp_local += -0.5f*z*z - logf(sigma) - 0.91893853320467274f;
        g_mu[idx*5 + j] = mu;
    }

    #pragma unroll
    for (int p = 0; p < 5; p++) {
        float sc[5];
        #pragma unroll
        for (int j = 0; j < 5; j++) {
            if (j > p) { sc[j] = -1e9f; continue; }
            float d = 0.f;
            #pragma unroll
            for (int c = 0; c < 5; c++) d += cq[p][c]*ck[j][c];
            sc[j] = d*0.2f;
        }
        float mx = sc[0];
        #pragma unroll
        for (int j = 1; j < 5; j++) mx = fmaxf(mx, sc[j]);
        float se = 0.f, ew[5];
        #pragma unroll
        for (int j = 0; j < 5; j++) { ew[j] = expf(sc[j]-mx); se += ew[j]; }
        float inv = 1.f/se;
        #pragma unroll
        for (int c = 0; c < 5; c++) {
            float v = 0.f;
            #pragma unroll
            for (int j = 0; j < 5; j++) v += ew[j]*cq[j][c];
            g_q2[idx*25 + p*5 + c] = v*inv;
        }
    }

    #pragma unroll
    for (int off = 16; off; off >>= 1)
        lp_local += __shfl_down_sync(0xffffffff, lp_local, off);
    if ((threadIdx.x & 31) == 0) atomicAdd(&g_lp_sum, lp_local);
}

// ---------------- kernel 3: warp-cooperative fused conv_back + u2-sum --------
__global__ void __launch_bounds__(1024) k_proj(const float* __restrict__ wpb,
                                               const float* __restrict__ bpb) {
    extern __shared__ float smp[];
    float* q2s = smp;            // 1024 rows x 28
    float* wsh = smp + 28672;    // 512 rows x 16
    int blk = blockIdx.x;
    int qtr = blk & 3;
    int hh  = (blk >> 2) & 7;
    int bb  = blk >> 5;

    const float* q2b = g_q2 + (bb << 10)*25;
    for (int i = threadIdx.x; i < 25600; i += 1024) {
        int row = i / 25;
        int col = i - row*25;
        q2s[row*28 + col] = q2b[i];
    }
    for (int i = threadIdx.x; i < 512*16; i += 1024) {
        int c = i >> 4, e = i & 15;
        wsh[i] = (e < 15) ? __ldg(&wpb[c*15 + e]) : __ldg(&bpb[c]);
    }
    __syncthreads();

    int p0 = qtr*3277;
    int p1 = min(p0 + 3277, 13108);
    size_t obase = (size_t)(bb*8 + hh)*65536;
    int warp = threadIdx.x >> 5, lane = threadIdx.x & 31;

    for (int kb = p0 + warp*31; kb < p1; kb += 32*31) {
        int k = kb + lane;
        float acc[5] = {0.f, 0.f, 0.f, 0.f, 0.f};

        #pragma unroll
        for (int u2 = 0; u2 < 5; u2++) {
            int kw = min(kb + lane, 13107);
            int W  = (hh*5 + u2)*13107 + hh + kw;
            int c  = W >> 10, ll = W & 1023;

            const float4* qp = (const float4*)(q2s + ll*28);
            float4 q0 = qp[0], q1 = qp[1], q2v = qp[2],
                   q3 = qp[3], q4 = qp[4], q5 = qp[5];
            float q24 = q2s[ll*28 + 24];
            const float4* wp = (const float4*)(wsh + c*16);
            float4 w0 = wp[0], w1 = wp[1], w2 = wp[2], w3 = wp[3];

            float qr[25] = {q0.x,q0.y,q0.z,q0.w, q1.x,q1.y,q1.z,q1.w,
                            q2v.x,q2v.y,q2v.z,q2v.w, q3.x,q3.y,q3.z,q3.w,
                            q4.x,q4.y,q4.z,q4.w, q5.x,q5.y,q5.z,q5.w, q24};
            float wr[15] = {w0.x,w0.y,w0.z,w0.w, w1.x,w1.y,w1.z,w1.w,
                            w2.x,w2.y,w2.z,w2.w, w3.x,w3.y,w3.z};
            float bias = w3.w;

            float Dm[5][3];
            #pragma unroll
            for (int jj = 0; jj < 5; jj++)
                #pragma unroll
                for (int t = 0; t < 3; t++) {
                    float d = 0.f;
                    #pragma unroll
                    for (int nc = 0; nc < 5; nc++)
                        d += qr[jj*5 + nc]*wr[nc*3 + t];
                    Dm[jj][t] = d;
                }
            float y[5];
            #pragma unroll
            for (int j = 0; j < 5; j++) {
                float v = bias + Dm[j][1];
                if (j >= 1) v += Dm[j-1][0];
                if (j <= 3) v += Dm[j+1][2];
                y[j] = fmaxf(v, 0.f);
            }

            float ynx[5];
            #pragma unroll
            for (int j = 0; j < 5; j++)
                ynx[j] = __shfl_down_sync(0xffffffffu, y[j], 1);

            #pragma unroll
            for (int i = 0; i < 5; i++)
                acc[i] += (u2 + i < 5) ? y[u2 + i] : ynx[i - 5 + u2];
        }

        if (lane < 31 && k < p1) {
            int pos0 = k*5;
            int valid = min(5, 65536 - pos0);
            #pragma unroll
            for (int i = 0; i < 5; i++)
                if (i < valid) {
                    __half h = __float2half_rn(acc[i]);
                    g_kh[obase + pos0 + i] = h;
                    g_kl[obase + pos0 + i] = __float2half_rn(acc[i] - __half2float(h));
                }
        }
    }
}

// ---------------- kernel 5: CE term ------------------------------------------
__global__ void k_ce() {
    int bb = blockIdx.x / 5, j = blockIdx.x % 5;
    const float* base = g_mu + (bb << 10)*5 + j;
    __shared__ float sh[256];
    int tid = threadIdx.x;

    float mx = -1e30f;
    for (int ll = tid; ll < L_; ll += 256) mx = fmaxf(mx, base[ll*5]);
    sh[tid] = mx; __syncthreads();
    for (int s = 128; s > 0; s >>= 1) { if (tid < s) sh[tid] = fmaxf(sh[tid], sh[tid+s]); __syncthreads(); }
    mx = sh[0]; __syncthreads();

    float se = 0.f;
    for (int ll = tid; ll < L_; ll += 256) se += expf(base[ll*5] - mx);
    sh[tid] = se; __syncthreads();
    for (int s = 128; s > 0; s >>= 1) { if (tid < s) sh[tid] += sh[tid+s]; __syncthreads(); }
    float lse = mx + logf(sh[0]); __syncthreads();

    float acc = 0.f;
    for (int ll = tid; ll < L_; ll += 256) { float m = base[ll*5]; acc += m*(m - lse); }
    sh[tid] = acc; __syncthreads();
    for (int s = 128; s > 0; s >>= 1) { if (tid < s) sh[tid] += sh[tid+s]; __syncthreads(); }
    if (tid == 0) atomicAdd(&g_ce_sum, sh[0]);
}

__global__ void k_loss(float* out, int n) {
    out[n] = -(g_lp_sum / 40960.f) - (g_ce_sum / 40.f);
}

// ---------------- kernel 4: flash attention (R13 structure, prefetch hoisted)
__device__ __forceinline__ void mma16816(float d[4], const uint32_t a[4], const uint32_t b0, const uint32_t b1) {
    asm volatile("mma.sync.aligned.m16n8k16.row.col.f32.f16.f16.f32 "
                 "{%0,%1,%2,%3}, {%4,%5,%6,%7}, {%8,%9}, {%0,%1,%2,%3};\n"
                 : "+f"(d[0]), "+f"(d[1]), "+f"(d[2]), "+f"(d[3])
                 : "r"(a[0]), "r"(a[1]), "r"(a[2]), "r"(a[3]), "r"(b0), "r"(b1));
}
__device__ __forceinline__ void ldm4(uint32_t r[4], uint32_t addr) {
    asm volatile("ldmatrix.sync.aligned.m8n8.x4.shared.b16 {%0,%1,%2,%3}, [%4];\n"
                 : "=r"(r[0]), "=r"(r[1]), "=r"(r[2]), "=r"(r[3]) : "r"(addr));
}
__device__ __forceinline__ uint32_t packh(__half x, __half y) {
    __half2 h = __halves2half2(x, y);
    return *reinterpret_cast<uint32_t*>(&h);
}
__device__ __forceinline__ void split2(float2 f, uint32_t& hi, uint32_t& lo) {
    __half hx = __float2half_rn(f.x), hy = __float2half_rn(f.y);
    __half lx = __float2half_rn(f.x - __half2float(hx));
    __half ly = __float2half_rn(f.y - __half2float(hy));
    hi = packh(hx, hy); lo = packh(lx, ly);
}
__device__ __forceinline__ float ex2(float x) {
    float y; asm("ex2.approx.f32 %0, %1;" : "=f"(y) : "f"(x)); return y;
}
__device__ __forceinline__ void cpasync16(uint32_t smem_addr, const void* gptr) {
    asm volatile("cp.async.cg.shared.global [%0], [%1], 16;\n" :: "r"(smem_addr), "l"(gptr));
}

#define PADT 72
#define TILE_H (64*PADT)
#define STAGE_B (3*TILE_H*2)

__global__ void __launch_bounds__(256, 2) k_attn(const float* __restrict__ Q,
                                                 float* __restrict__ out) {
    extern __shared__ __half sm[];
    int bh = blockIdx.x >> 3, qt = blockIdx.x & 7;
    int tid = threadIdx.x, w = tid >> 5, lane = tid & 31;
    int g = lane >> 2, c4 = lane & 3;

    const __half* khg = g_kh + (size_t)bh*L_*D_;
    const __half* klg = g_kl + (size_t)bh*L_*D_;
    const __half* vhg = g_vh + (size_t)bh*D_*L_;

    const float LOG2E = 1.44269504088896340736f;
    uint32_t qfh[4][4], qfl[4][4];
    const float* Qb = Q + ((size_t)bh*L_ + qt*128 + w*16)*D_;
    #pragma unroll
    for (int kc = 0; kc < 4; kc++) {
        int col0 = kc*16 + 2*c4;
        float2 a0 = *(const float2*)(Qb + g*D_     + col0);
        float2 a1 = *(const float2*)(Qb + (g+8)*D_ + col0);
        float2 a2 = *(const float2*)(Qb + g*D_     + col0 + 8);
        float2 a3 = *(const float2*)(Qb + (g+8)*D_ + col0 + 8);
        a0.x *= LOG2E; a0.y *= LOG2E; a1.x *= LOG2E; a1.y *= LOG2E;
        a2.x *= LOG2E; a2.y *= LOG2E; a3.x *= LOG2E; a3.y *= LOG2E;
        split2(a0, qfh[kc][0], qfl[kc][0]);
        split2(a1, qfh[kc][1], qfl[kc][1]);
        split2(a2, qfh[kc][2], qfl[kc][2]);
        split2(a3, qfh[kc][3], qfl[kc][3]);
    }

    float o[8][4];
    #pragma unroll
    for (int i = 0; i < 8; i++)
        #pragma unroll
        for (int e = 0; e < 4; e++) o[i][e] = 0.f;
    float m0 = -1e30f, m1 = -1e30f, l0 = 0.f, l1 = 0.f;

    uint32_t smbase = (uint32_t)__cvta_generic_to_shared(sm);
    int lrow = ((lane >> 4) << 3) + (lane & 7);
    uint32_t lsel = ((lane >> 3) & 1) << 3;
    uint32_t laneoff = (uint32_t)(lrow*PADT + lsel)*2;

    auto stage = [&](int kt, int s) {
        uint32_t b = smbase + (uint32_t)s*STAGE_B;
        #pragma unroll
        for (int i = tid; i < 1536; i += 256) {
            int arr = i >> 9, j = i & 511;
            int r = j >> 3, ch = j & 7;
            const __half* src;
            if (arr == 0)      src = khg + kt*4096 + r*64 + ch*8;
            else if (arr == 1) src = klg + kt*4096 + r*64 + ch*8;
            else               src = vhg + r*1024 + kt*64 + ch*8;
            cpasync16(b + (uint32_t)arr*(TILE_H*2) + (uint32_t)(r*PADT + ch*8)*2, src);
        }
    };

    stage(0, 0);
    asm volatile("cp.async.commit_group;\n");
    stage(1, 1);
    asm volatile("cp.async.commit_group;\n");

    int bufA = 0, bufB = 1, bufC = 2;
    for (int kt = 0; kt < 16; kt++) {
        asm volatile("cp.async.wait_group 1;\n");
        __syncthreads();

        // prefetch kt+2 first: bufC's readers are behind the barrier above
        if (kt < 14) stage(kt+2, bufC);
        asm volatile("cp.async.commit_group;\n");

        uint32_t kh_b = smbase + (uint32_t)bufA*STAGE_B + laneoff;
        uint32_t kl_b = kh_b + TILE_H*2;
        uint32_t vh_b = kl_b + TILE_H*2;

        #pragma unroll
        for (int hf = 0; hf < 2; hf++) {
            float s[4][4];
            #pragma unroll
            for (int nt = 0; nt < 4; nt++)
                #pragma unroll
                for (int e = 0; e < 4; e++) s[nt][e] = 0.f;

            #pragma unroll
            for (int kc = 0; kc < 4; kc++) {
                #pragma unroll
                for (int np = 0; np < 2; np++) {
                    uint32_t off = (uint32_t)((hf*32 + np*16)*PADT + kc*16)*2;
                    uint32_t bhm[4], blm[4];
                    ldm4(bhm, kh_b + off);
                    ldm4(blm, kl_b + off);
                    mma16816(s[np*2],   qfh[kc], bhm[0], bhm[1]);
                    mma16816(s[np*2],   qfl[kc], bhm[0], bhm[1]);
                    mma16816(s[np*2],   qfh[kc], blm[0], blm[1]);
                    mma16816(s[np*2+1], qfh[kc], bhm[2], bhm[3]);
                    mma16816(s[np*2+1], qfl[kc], bhm[2], bhm[3]);
                    mma16816(s[np*2+1], qfh[kc], blm[2], blm[3]);
                }
            }

            // online softmax in exp2 domain (rows g, g+8)
            float mt0 = s[0][0], mt1 = s[0][2];
            #pragma unroll
            for (int nt = 0; nt < 4; nt++) {
                mt0 = fmaxf(mt0, fmaxf(s[nt][0], s[nt][1]));
                mt1 = fmaxf(mt1, fmaxf(s[nt][2], s[nt][3]));
            }
            mt0 = fmaxf(mt0, __shfl_xor_sync(0xffffffff, mt0, 1));
            mt0 = fmaxf(mt0, __shfl_xor_sync(0xffffffff, mt0, 2));
            mt1 = fmaxf(mt1, __shfl_xor_sync(0xffffffff, mt1, 1));
            mt1 = fmaxf(mt1, __shfl_xor_sync(0xffffffff, mt1, 2));
            float m0n = fmaxf(m0, mt0), m1n = fmaxf(m1, mt1);
            bool need = (m0n > m0) || (m1n > m1);
            if (__ballot_sync(0xffffffffu, need)) {
                float sc0 = ex2(m0 - m0n), sc1 = ex2(m1 - m1n);
                l0 *= sc0; l1 *= sc1;
                #pragma unroll
                for (int i = 0; i < 8; i++) {
                    o[i][0] *= sc0; o[i][1] *= sc0;
                    o[i][2] *= sc1; o[i][3] *= sc1;
                }
            }
            m0 = m0n; m1 = m1n;

            uint32_t PH[4][2];
            #pragma unroll
            for (int nt = 0; nt < 4; nt++) {
                float p0 = ex2(s[nt][0] - m0), p1 = ex2(s[nt][1] - m0);
                float p2 = ex2(s[nt][2] - m1), p3 = ex2(s[nt][3] - m1);
                l0 += p0 + p1; l1 += p2 + p3;
                PH[nt][0] = packh(__float2half_rn(p0), __float2half_rn(p1));
                PH[nt][1] = packh(__float2half_rn(p2), __float2half_rn(p3));
            }

            #pragma unroll
            for (int kc2 = 0; kc2 < 2; kc2++) {
                uint32_t Ah[4] = {PH[2*kc2][0], PH[2*kc2][1], PH[2*kc2+1][0], PH[2*kc2+1][1]};
                #pragma unroll
                for (int np = 0; np < 4; np++) {
                    uint32_t off = (uint32_t)(np*16*PADT + hf*32 + kc2*16)*2;
                    uint32_t bvm[4];
                    ldm4(bvm, vh_b + off);
                    mma16816(o[np*2],   Ah, bvm[0], bvm[1]);
                    mma16816(o[np*2+1], Ah, bvm[2], bvm[3]);
                }
            }
        }

        int tmp = bufA; bufA = bufB; bufB = bufC; bufC = tmp;
    }

    l0 += __shfl_xor_sync(0xffffffff, l0, 1);
    l0 += __shfl_xor_sync(0xffffffff, l0, 2);
    l1 += __shfl_xor_sync(0xffffffff, l1, 1);
    l1 += __shfl_xor_sync(0xffffffff, l1, 2);
    float inv0 = 1.f/l0, inv1 = 1.f/l1;

    float* Ob = out + ((size_t)bh*L_ + qt*128 + w*16)*D_;
    #pragma unroll
    for (int nt = 0; nt < 8; nt++) {
        int col = nt*8 + 2*c4;
        *(float2*)(Ob + g*D_     + col) = make_float2(o[nt][0]*inv0, o[nt][1]*inv0);
        *(float2*)(Ob + (g+8)*D_ + col) = make_float2(o[nt][2]*inv1, o[nt][3]*inv1);
    }
}

// ---------------- launcher ---------------------------------------------------
extern "C" void kernel_launch(void* const* d_in, const int* in_sizes, int n_in,
                              void* d_out, int out_size) {
    const float* Q   = (const float*)d_in[0];
    const float* K   = (const float*)d_in[1];
    const float* V   = (const float*)d_in[2];
    const float* wpk = (const float*)d_in[3];
    const float* bpk = (const float*)d_in[4];
    const float* wpb = (const float*)d_in[5];
    const float* bpb = (const float*)d_in[6];
    const float* wck = (const float*)d_in[7];
    const float* bck = (const float*)d_in[8];
    const float* wcq = (const float*)d_in[9];
    const float* bcq = (const float*)d_in[10];
    float* out = (float*)d_out;

    const int ATTN_SMEM = 3*STAGE_B;                 // 82944 B
    const int PROJ_SMEM = (1024*28 + 512*16)*4;      // 147456 B
    cudaFuncSetAttribute(k_attn, cudaFuncAttributeMaxDynamicSharedMemorySize, ATTN_SMEM);
    cudaFuncSetAttribute(k_proj, cudaFuncAttributeMaxDynamicSharedMemorySize, PROJ_SMEM);

    k_prep<<<128 + B_*H_*8, 512>>>(K, wpk, V);            // 1
    k_small<<<(B_*L_)/64, 64>>>(bpk, wck, bck, wcq, bcq); // 2
    k_proj<<<B_*H_*4, 1024, PROJ_SMEM>>>(wpb, bpb);       // 3
    k_attn<<<B_*H_*8, 256, ATTN_SMEM>>>(Q, out);          // 4
    k_ce<<<B_*NC_, 256>>>();                              // 5
    const int N = B_*H_*L_*D_;
    if (out_size > N) k_loss<<<1, 1>>>(out, N);           // 6
}

// round 16
// speedup vs baseline: 1.0434x; 1.0322x over previous
#include <cuda_runtime.h>
#include <cuda_fp16.h>
#include <math.h>
#include <stdint.h>

#define B_  8
#define H_  8
#define L_  1024
#define D_  64
#define DM_ 512
#define NC_ 5

// ---------------- scratch (__device__ globals; no allocation) ----------------
__device__ float g_G[B_*15*L_];        // TRANSPOSED: G[bs][i=nc*3+t][ll2]
__device__ float g_q2[B_*L_*25];       // cluster_q2[bb][ll2][p*5+c]
__device__ float g_mu[B_*L_*NC_];      // mu[bb][ll2][j]
__device__ __half g_kh[B_*H_*L_*D_];   // KK split hi   [bh][key][dim]
__device__ __half g_kl[B_*H_*L_*D_];   // KK split lo
__device__ __half g_vh[B_*H_*D_*L_];   // V^T fp16 (hi) [bh][dim][key]
__device__ float g_lp_sum;
__device__ float g_ce_sum;

// ---------------- kernel 1 (MERGED): gmat (blocks 0..127) + vprep (128..639) -
__global__ void __launch_bounds__(512) k_prep(const float* __restrict__ K,
                                              const float* __restrict__ wk,
                                              const float* __restrict__ V) {
    __shared__ float sh[128*65];
    int blk = blockIdx.x;
    if (blk == 0 && threadIdx.x == 0) { g_lp_sum = 0.f; g_ce_sum = 0.f; }

    if (blk < 128) {
        int bs  = blk >> 4;
        int gg  = blk & 15;
        int q   = threadIdx.x & 63;
        int cg  = threadIdx.x >> 6;
        float (*red)[64][15] = (float(*)[64][15])sh;

        float acc[15];
        #pragma unroll
        for (int i = 0; i < 15; i++) acc[i] = 0.f;

        for (int c = cg*64; c < cg*64 + 64; c++) {
            int hh = c >> 6;
            int m  = c & 63;
            float kv = K[(((bs*H_ + hh)*L_) + m*16 + gg)*D_ + q];
            #pragma unroll
            for (int nc = 0; nc < 5; nc++)
                #pragma unroll
                for (int t = 0; t < 3; t++)
                    acc[nc*3+t] += kv * __ldg(&wk[nc*1536 + c*3 + t]);
        }

        #pragma unroll
        for (int i = 0; i < 15; i++) red[cg][q][i] = acc[i];
        __syncthreads();
        if (cg == 0) {
            int ll2 = gg*64 + q;
            #pragma unroll
            for (int i = 0; i < 15; i++) {
                float s = 0.f;
                #pragma unroll
                for (int r = 0; r < 8; r++) s += red[r][q][i];
                g_G[(bs*15 + i)*L_ + ll2] = s;   // transposed, coalesced across q
            }
        }
    } else {
        int vb = blk - 128;
        int bh = vb >> 3, ch = vb & 7;
        const float* Vb = V + ((size_t)bh*L_ + ch*128)*D_;
        float (*t)[65] = (float(*)[65])sh;
        for (int i = threadIdx.x; i < 128*64/4; i += 512) {
            float4 v4 = ((const float4*)Vb)[i];
            int r = i >> 4, cl = (i & 15)*4;
            t[r][cl] = v4.x; t[r][cl+1] = v4.y; t[r][cl+2] = v4.z; t[r][cl+3] = v4.w;
        }
        __syncthreads();
        for (int i = threadIdx.x; i < 64*128; i += 512) {
            int d = i >> 7, key = i & 127;
            g_vh[((size_t)bh*64 + d)*1024 + ch*128 + key] = __float2half_rn(t[key][d]);
        }
    }
}

// ---------------- kernel 2: per-(bb,ll2) cluster math + loss partials --------
__global__ void k_small(const float* __restrict__ bk,
                        const float* __restrict__ wck, const float* __restrict__ bck,
                        const float* __restrict__ wcq, const float* __restrict__ bcq) {
    int idx = blockIdx.x*blockDim.x + threadIdx.x;
    int bb = idx >> 10, ll = idx & 1023;

    float ckp[5][5];
    #pragma unroll
    for (int j = 0; j < 5; j++)
        #pragma unroll
        for (int nc = 0; nc < 5; nc++) {
            float a = bk[nc];
            #pragma unroll
            for (int t = 0; t < 3; t++) {
                int jj = j + t - 1;
                if (jj >= 0 && jj < 5) {
                    int bs = bb + jj - 4;
                    if (bs >= 1) a += g_G[(bs*15 + nc*3 + t)*L_ + ll];  // coalesced
                }
            }
            ckp[j][nc] = fmaxf(a, 0.f);
        }

    float ck[5][5], cq[5][5];
    float lp_local = 0.f;
    #pragma unroll
    for (int j = 0; j < 5; j++) {
        float zk[5], zq[5];
        #pragma unroll
        for (int o = 0; o < 5; o++) {
            float sk = bck[o], sq = bcq[o];
            #pragma unroll
            for (int nc = 0; nc < 5; nc++) {
                sk += ckp[j][nc]*wck[o*5+nc];
                sq += ckp[j][nc]*wcq[o*5+nc];
            }
            zk[o] = sk; zq[o] = sq;
        }
        float mk = zk[0], mq = zq[0];
        #pragma unroll
        for (int o = 1; o < 5; o++) { mk = fmaxf(mk, zk[o]); mq = fmaxf(mq, zq[o]); }
        float sks = 0.f, sqs = 0.f;
        #pragma unroll
        for (int o = 0; o < 5; o++) {
            float ek = expf(zk[o]-mk), eq = expf(zq[o]-mq);
            ck[j][o] = ek; cq[j][o] = eq; sks += ek; sqs += eq;
        }
        float ik = 1.f/sks, iq = 1.f/sqs;
        #pragma unroll
        for (int o = 0; o < 5; o++) { ck[j][o] *= ik; cq[j][o] *= iq; }

        float mu = 0.f, x = 0.f;
        #pragma unroll
        for (int o = 0; o < 5; o++) { mu += cq[j][o]; x += ck[j][o]; }
        mu *= 0.2f; x *= 0.2f;
        float var = 0.f;
        #pragma unroll
        for (int o = 0; o < 5; o++) { float d = cq[j][o]-mu; var += d*d; }
        var *= 0.25f;
        float sd    = sqrtf(var);
        float sigma = logf(1.f + expf(sd));
        float z     = (x - mu)/sigma;
        lp_local += -0.5f*z*z - logf(sigma) - 0.91893853320467274f;
        g_mu[idx*5 + j] = mu;
    }

    #pragma unroll
    for (int p = 0; p < 5; p++) {
        float sc[5];
        #pragma unroll
        for (int j = 0; j < 5; j++) {
            if (j > p) { sc[j] = -1e9f; continue; }
            float d = 0.f;
            #pragma unroll
            for (int c = 0; c < 5; c++) d += cq[p][c]*ck[j][c];
            sc[j] = d*0.2f;
        }
        float mx = sc[0];
        #pragma unroll
        for (int j = 1; j < 5; j++) mx = fmaxf(mx, sc[j]);
        float se = 0.f, ew[5];
        #pragma unroll
        for (int j = 0; j < 5; j++) { ew[j] = expf(sc[j]-mx); se += ew[j]; }
        float inv = 1.f/se;
        #pragma unroll
        for (int c = 0; c < 5; c++) {
            float v = 0.f;
            #pragma unroll
            for (int j = 0; j < 5; j++) v += ew[j]*cq[j][c];
            g_q2[idx*25 + p*5 + c] = v*inv;
        }
    }

    #pragma unroll
    for (int off = 16; off; off >>= 1)
        lp_local += __shfl_down_sync(0xffffffff, lp_local, off);
    if ((threadIdx.x & 31) == 0) atomicAdd(&g_lp_sum, lp_local);
}

// ---------------- kernel 3: warp-cooperative fused conv_back + u2-sum --------
__global__ void __launch_bounds__(1024) k_proj(const float* __restrict__ wpb,
                                               const float* __restrict__ bpb) {
    extern __shared__ float smp[];
    float* q2s = smp;            // 1024 rows x 28
    float* wsh = smp + 28672;    // 512 rows x 16
    int blk = blockIdx.x;
    int qtr = blk & 3;
    int hh  = (blk >> 2) & 7;
    int bb  = blk >> 5;

    const float* q2b = g_q2 + (bb << 10)*25;
    for (int i = threadIdx.x; i < 25600; i += 1024) {
        int row = i / 25;
        int col = i - row*25;
        q2s[row*28 + col] = q2b[i];
    }
    for (int i = threadIdx.x; i < 512*16; i += 1024) {
        int c = i >> 4, e = i & 15;
        wsh[i] = (e < 15) ? __ldg(&wpb[c*15 + e]) : __ldg(&bpb[c]);
    }
    __syncthreads();

    int p0 = qtr*3277;
    int p1 = min(p0 + 3277, 13108);
    size_t obase = (size_t)(bb*8 + hh)*65536;
    int warp = threadIdx.x >> 5, lane = threadIdx.x & 31;

    for (int kb = p0 + warp*31; kb < p1; kb += 32*31) {
        int k = kb + lane;
        float acc[5] = {0.f, 0.f, 0.f, 0.f, 0.f};

        #pragma unroll
        for (int u2 = 0; u2 < 5; u2++) {
            int kw = min(kb + lane, 13107);
            int W  = (hh*5 + u2)*13107 + hh + kw;
            int c  = W >> 10, ll = W & 1023;

            const float4* qp = (const float4*)(q2s + ll*28);
            float4 q0 = qp[0], q1 = qp[1], q2v = qp[2],
                   q3 = qp[3], q4 = qp[4], q5 = qp[5];
            float q24 = q2s[ll*28 + 24];
            const float4* wp = (const float4*)(wsh + c*16);
            float4 w0 = wp[0], w1 = wp[1], w2 = wp[2], w3 = wp[3];

            float qr[25] = {q0.x,q0.y,q0.z,q0.w, q1.x,q1.y,q1.z,q1.w,
                            q2v.x,q2v.y,q2v.z,q2v.w, q3.x,q3.y,q3.z,q3.w,
                            q4.x,q4.y,q4.z,q4.w, q5.x,q5.y,q5.z,q5.w, q24};
            float wr[15] = {w0.x,w0.y,w0.z,w0.w, w1.x,w1.y,w1.z,w1.w,
                            w2.x,w2.y,w2.z,w2.w, w3.x,w3.y,w3.z};
            float bias = w3.w;

            float Dm[5][3];
            #pragma unroll
            for (int jj = 0; jj < 5; jj++)
                #pragma unroll
                for (int t = 0; t < 3; t++) {
                    float d = 0.f;
                    #pragma unroll
                    for (int nc = 0; nc < 5; nc++)
                        d += qr[jj*5 + nc]*wr[nc*3 + t];
                    Dm[jj][t] = d;
                }
            float y[5];
            #pragma unroll
            for (int j = 0; j < 5; j++) {
                float v = bias + Dm[j][1];
                if (j >= 1) v += Dm[j-1][0];
                if (j <= 3) v += Dm[j+1][2];
                y[j] = fmaxf(v, 0.f);
            }

            float ynx[5];
            #pragma unroll
            for (int j = 0; j < 5; j++)
                ynx[j] = __shfl_down_sync(0xffffffffu, y[j], 1);

            #pragma unroll
            for (int i = 0; i < 5; i++)
                acc[i] += (u2 + i < 5) ? y[u2 + i] : ynx[i - 5 + u2];
        }

        if (lane < 31 && k < p1) {
            int pos0 = k*5;
            int valid = min(5, 65536 - pos0);
            #pragma unroll
            for (int i = 0; i < 5; i++)
                if (i < valid) {
                    __half h = __float2half_rn(acc[i]);
                    g_kh[obase + pos0 + i] = h;
                    g_kl[obase + pos0 + i] = __float2half_rn(acc[i] - __half2float(h));
                }
        }
    }
}

// ---------------- kernel 5: CE term ------------------------------------------
__global__ void k_ce() {
    int bb = blockIdx.x / 5, j = blockIdx.x % 5;
    const float* base = g_mu + (bb << 10)*5 + j;
    __shared__ float sh[256];
    int tid = threadIdx.x;

    float mx = -1e30f;
    for (int ll = tid; ll < L_; ll += 256) mx = fmaxf(mx, base[ll*5]);
    sh[tid] = mx; __syncthreads();
    for (int s = 128; s > 0; s >>= 1) { if (tid < s) sh[tid] = fmaxf(sh[tid], sh[tid+s]); __syncthreads(); }
    mx = sh[0]; __syncthreads();

    float se = 0.f;
    for (int ll = tid; ll < L_; ll += 256) se += expf(base[ll*5] - mx);
    sh[tid] = se; __syncthreads();
    for (int s = 128; s > 0; s >>= 1) { if (tid < s) sh[tid] += sh[tid+s]; __syncthreads(); }
    float lse = mx + logf(sh[0]); __syncthreads();

    float acc = 0.f;
    for (int ll = tid; ll < L_; ll += 256) { float m = base[ll*5]; acc += m*(m - lse); }
    sh[tid] = acc; __syncthreads();
    for (int s = 128; s > 0; s >>= 1) { if (tid < s) sh[tid] += sh[tid+s]; __syncthreads(); }
    if (tid == 0) atomicAdd(&g_ce_sum, sh[0]);
}

__global__ void k_loss(float* out, int n) {
    out[n] = -(g_lp_sum / 40960.f) - (g_ce_sum / 40.f);
}

// ---------------- kernel 4: flash attention (EXACT R13 structure) ------------
__device__ __forceinline__ void mma16816(float d[4], const uint32_t a[4], const uint32_t b0, const uint32_t b1) {
    asm volatile("mma.sync.aligned.m16n8k16.row.col.f32.f16.f16.f32 "
                 "{%0,%1,%2,%3}, {%4,%5,%6,%7}, {%8,%9}, {%0,%1,%2,%3};\n"
                 : "+f"(d[0]), "+f"(d[1]), "+f"(d[2]), "+f"(d[3])
                 : "r"(a[0]), "r"(a[1]), "r"(a[2]), "r"(a[3]), "r"(b0), "r"(b1));
}
__device__ __forceinline__ void ldm4(uint32_t r[4], uint32_t addr) {
    asm volatile("ldmatrix.sync.aligned.m8n8.x4.shared.b16 {%0,%1,%2,%3}, [%4];\n"
                 : "=r"(r[0]), "=r"(r[1]), "=r"(r[2]), "=r"(r[3]) : "r"(addr));
}
__device__ __forceinline__ uint32_t packh(__half x, __half y) {
    __half2 h = __halves2half2(x, y);
    return *reinterpret_cast<uint32_t*>(&h);
}
__device__ __forceinline__ void split2(float2 f, uint32_t& hi, uint32_t& lo) {
    __half hx = __float2half_rn(f.x), hy = __float2half_rn(f.y);
    __half lx = __float2half_rn(f.x - __half2float(hx));
    __half ly = __float2half_rn(f.y - __half2float(hy));
    hi = packh(hx, hy); lo = packh(lx, ly);
}
__device__ __forceinline__ float ex2(float x) {
    float y; asm("ex2.approx.f32 %0, %1;" : "=f"(y) : "f"(x)); return y;
}
__device__ __forceinline__ void cpasync16(uint32_t smem_addr, const void* gptr) {
    asm volatile("cp.async.cg.shared.global [%0], [%1], 16;\n" :: "r"(smem_addr), "l"(gptr));
}

#define PADT 72
#define TILE_H (64*PADT)
#define STAGE_B (3*TILE_H*2)

__global__ void __launch_bounds__(256, 2) k_attn(const float* __restrict__ Q,
                                                 float* __restrict__ out) {
    extern __shared__ __half sm[];
    int bh = blockIdx.x >> 3, qt = blockIdx.x & 7;
    int tid = threadIdx.x, w = tid >> 5, lane = tid & 31;
    int g = lane >> 2, c4 = lane & 3;

    const __half* khg = g_kh + (size_t)bh*L_*D_;
    const __half* klg = g_kl + (size_t)bh*L_*D_;
    const __half* vhg = g_vh + (size_t)bh*D_*L_;

    const float LOG2E = 1.44269504088896340736f;
    uint32_t qfh[4][4], qfl[4][4];
    const float* Qb = Q + ((size_t)bh*L_ + qt*128 + w*16)*D_;
    #pragma unroll
    for (int kc = 0; kc < 4; kc++) {
        int col0 = kc*16 + 2*c4;
        float2 a0 = *(const float2*)(Qb + g*D_     + col0);
        float2 a1 = *(const float2*)(Qb + (g+8)*D_ + col0);
        float2 a2 = *(const float2*)(Qb + g*D_     + col0 + 8);
        float2 a3 = *(const float2*)(Qb + (g+8)*D_ + col0 + 8);
        a0.x *= LOG2E; a0.y *= LOG2E; a1.x *= LOG2E; a1.y *= LOG2E;
        a2.x *= LOG2E; a2.y *= LOG2E; a3.x *= LOG2E; a3.y *= LOG2E;
        split2(a0, qfh[kc][0], qfl[kc][0]);
        split2(a1, qfh[kc][1], qfl[kc][1]);
        split2(a2, qfh[kc][2], qfl[kc][2]);
        split2(a3, qfh[kc][3], qfl[kc][3]);
    }

    float o[8][4];
    #pragma unroll
    for (int i = 0; i < 8; i++)
        #pragma unroll
        for (int e = 0; e < 4; e++) o[i][e] = 0.f;
    float m0 = -1e30f, m1 = -1e30f, l0 = 0.f, l1 = 0.f;

    uint32_t smbase = (uint32_t)__cvta_generic_to_shared(sm);
    int lrow = ((lane >> 4) << 3) + (lane & 7);
    uint32_t lsel = ((lane >> 3) & 1) << 3;
    uint32_t laneoff = (uint32_t)(lrow*PADT + lsel)*2;

    auto stage = [&](int kt, int s) {
        uint32_t b = smbase + (uint32_t)s*STAGE_B;
        #pragma unroll
        for (int i = tid; i < 1536; i += 256) {
            int arr = i >> 9, j = i & 511;
            int r = j >> 3, ch = j & 7;
            const __half* src;
            if (arr == 0)      src = khg + kt*4096 + r*64 + ch*8;
            else if (arr == 1) src = klg + kt*4096 + r*64 + ch*8;
            else               src = vhg + r*1024 + kt*64 + ch*8;
            cpasync16(b + (uint32_t)arr*(TILE_H*2) + (uint32_t)(r*PADT + ch*8)*2, src);
        }
    };

    stage(0, 0);
    asm volatile("cp.async.commit_group;\n");
    stage(1, 1);
    asm volatile("cp.async.commit_group;\n");

    int bufA = 0, bufB = 1, bufC = 2;
    for (int kt = 0; kt < 16; kt++) {
        asm volatile("cp.async.wait_group 1;\n");
        __syncthreads();

        uint32_t kh_b = smbase + (uint32_t)bufA*STAGE_B + laneoff;
        uint32_t kl_b = kh_b + TILE_H*2;
        uint32_t vh_b = kl_b + TILE_H*2;

        #pragma unroll
        for (int hf = 0; hf < 2; hf++) {
            float s[4][4];
            #pragma unroll
            for (int nt = 0; nt < 4; nt++)
                #pragma unroll
                for (int e = 0; e < 4; e++) s[nt][e] = 0.f;

            #pragma unroll
            for (int kc = 0; kc < 4; kc++) {
                #pragma unroll
                for (int np = 0; np < 2; np++) {
                    uint32_t off = (uint32_t)((hf*32 + np*16)*PADT + kc*16)*2;
                    uint32_t bhm[4], blm[4];
                    ldm4(bhm, kh_b + off);
                    ldm4(blm, kl_b + off);
                    mma16816(s[np*2],   qfh[kc], bhm[0], bhm[1]);
                    mma16816(s[np*2],   qfl[kc], bhm[0], bhm[1]);
                    mma16816(s[np*2],   qfh[kc], blm[0], blm[1]);
                    mma16816(s[np*2+1], qfh[kc], bhm[2], bhm[3]);
                    mma16816(s[np*2+1], qfl[kc], bhm[2], bhm[3]);
                    mma16816(s[np*2+1], qfh[kc], blm[2], blm[3]);
                }
            }

            // online softmax in exp2 domain (rows g, g+8)
            float mt0 = s[0][0], mt1 = s[0][2];
            #pragma unroll
            for (int nt = 0; nt < 4; nt++) {
                mt0 = fmaxf(mt0, fmaxf(s[nt][0], s[nt][1]));
                mt1 = fmaxf(mt1, fmaxf(s[nt][2], s[nt][3]));
            }
            mt0 = fmaxf(mt0, __shfl_xor_sync(0xffffffff, mt0, 1));
            mt0 = fmaxf(mt0, __shfl_xor_sync(0xffffffff, mt0, 2));
            mt1 = fmaxf(mt1, __shfl_xor_sync(0xffffffff, mt1, 1));
            mt1 = fmaxf(mt1, __shfl_xor_sync(0xffffffff, mt1, 2));
            float m0n = fmaxf(m0, mt0), m1n = fmaxf(m1, mt1);
            bool need = (m0n > m0) || (m1n > m1);
            if (__ballot_sync(0xffffffffu, need)) {
                float sc0 = ex2(m0 - m0n), sc1 = ex2(m1 - m1n);
                l0 *= sc0; l1 *= sc1;
                #pragma unroll
                for (int i = 0; i < 8; i++) {
                    o[i][0] *= sc0; o[i][1] *= sc0;
                    o[i][2] *= sc1; o[i][3] *= sc1;
                }
            }
            m0 = m0n; m1 = m1n;

            uint32_t PH[4][2];
            #pragma unroll
            for (int nt = 0; nt < 4; nt++) {
                float p0 = ex2(s[nt][0] - m0), p1 = ex2(s[nt][1] - m0);
                float p2 = ex2(s[nt][2] - m1), p3 = ex2(s[nt][3] - m1);
                l0 += p0 + p1; l1 += p2 + p3;
                PH[nt][0] = packh(__float2half_rn(p0), __float2half_rn(p1));
                PH[nt][1] = packh(__float2half_rn(p2), __float2half_rn(p3));
            }

            #pragma unroll
            for (int kc2 = 0; kc2 < 2; kc2++) {
                uint32_t Ah[4] = {PH[2*kc2][0], PH[2*kc2][1], PH[2*kc2+1][0], PH[2*kc2+1][1]};
                #pragma unroll
                for (int np = 0; np < 4; np++) {
                    uint32_t off = (uint32_t)(np*16*PADT + hf*32 + kc2*16)*2;
                    uint32_t bvm[4];
                    ldm4(bvm, vh_b + off);
                    mma16816(o[np*2],   Ah, bvm[0], bvm[1]);
                    mma16816(o[np*2+1], Ah, bvm[2], bvm[3]);
                }
            }
        }

        // stage tile kt+2 at END of body (R13 placement — measured best)
        if (kt < 14) stage(kt+2, bufC);
        asm volatile("cp.async.commit_group;\n");
        int tmp = bufA; bufA = bufB; bufB = bufC; bufC = tmp;
    }

    l0 += __shfl_xor_sync(0xffffffff, l0, 1);
    l0 += __shfl_xor_sync(0xffffffff, l0, 2);
    l1 += __shfl_xor_sync(0xffffffff, l1, 1);
    l1 += __shfl_xor_sync(0xffffffff, l1, 2);
    float inv0 = 1.f/l0, inv1 = 1.f/l1;

    float* Ob = out + ((size_t)bh*L_ + qt*128 + w*16)*D_;
    #pragma unroll
    for (int nt = 0; nt < 8; nt++) {
        int col = nt*8 + 2*c4;
        *(float2*)(Ob + g*D_     + col) = make_float2(o[nt][0]*inv0, o[nt][1]*inv0);
        *(float2*)(Ob + (g+8)*D_ + col) = make_float2(o[nt][2]*inv1, o[nt][3]*inv1);
    }
}

// ---------------- launcher ---------------------------------------------------
extern "C" void kernel_launch(void* const* d_in, const int* in_sizes, int n_in,
                              void* d_out, int out_size) {
    const float* Q   = (const float*)d_in[0];
    const float* K   = (const float*)d_in[1];
    const float* V   = (const float*)d_in[2];
    const float* wpk = (const float*)d_in[3];
    const float* bpk = (const float*)d_in[4];
    const float* wpb = (const float*)d_in[5];
    const float* bpb = (const float*)d_in[6];
    const float* wck = (const float*)d_in[7];
    const float* bck = (const float*)d_in[8];
    const float* wcq = (const float*)d_in[9];
    const float* bcq = (const float*)d_in[10];
    float* out = (float*)d_out;

    const int ATTN_SMEM = 3*STAGE_B;                 // 82944 B
    const int PROJ_SMEM = (1024*28 + 512*16)*4;      // 147456 B
    cudaFuncSetAttribute(k_attn, cudaFuncAttributeMaxDynamicSharedMemorySize, ATTN_SMEM);
    cudaFuncSetAttribute(k_proj, cudaFuncAttributeMaxDynamicSharedMemorySize, PROJ_SMEM);

    k_prep<<<128 + B_*H_*8, 512>>>(K, wpk, V);            // 1
    k_small<<<(B_*L_)/64, 64>>>(bpk, wck, bck, wcq, bcq); // 2
    k_proj<<<B_*H_*4, 1024, PROJ_SMEM>>>(wpb, bpb);       // 3
    k_attn<<<B_*H_*8, 256, ATTN_SMEM>>>(Q, out);          // 4
    k_ce<<<B_*NC_, 256>>>();                              // 5
    const int N = B_*H_*L_*D_;
    if (out_size > N) k_loss<<<1, 1>>>(out, N);           // 6
}

// round 17
// speedup vs baseline: 1.0618x; 1.0176x over previous
#include <cuda_runtime.h>
#include <cuda_fp16.h>
#include <math.h>
#include <stdint.h>

#define B_  8
#define H_  8
#define L_  1024
#define D_  64
#define DM_ 512
#define NC_ 5

// ---------------- scratch (__device__ globals; no allocation) ----------------
__device__ float g_G[B_*15*L_];        // TRANSPOSED: G[bs][i=nc*3+t][ll2]
__device__ float g_q2[B_*L_*25];       // cluster_q2[bb][ll2][p*5+c]
__device__ float g_mu[B_*L_*NC_];      // mu[bb][ll2][j]
__device__ __half g_kh[B_*H_*L_*D_];   // KK split hi   [bh][key][dim]
__device__ __half g_kl[B_*H_*L_*D_];   // KK split lo
__device__ __half g_vh[B_*H_*D_*L_];   // V^T fp16 (hi) [bh][dim][key]
__device__ float g_lp_sum;
__device__ float g_ce_sum;

// ---------------- kernel 1 (MERGED): gmat (blocks 0..127) + vprep (128..639) -
__global__ void __launch_bounds__(512) k_prep(const float* __restrict__ K,
                                              const float* __restrict__ wk,
                                              const float* __restrict__ V) {
    __shared__ float sh[128*65];
    int blk = blockIdx.x;
    if (blk == 0 && threadIdx.x == 0) { g_lp_sum = 0.f; g_ce_sum = 0.f; }

    if (blk < 128) {
        int bs  = blk >> 4;
        int gg  = blk & 15;
        int q   = threadIdx.x & 63;
        int cg  = threadIdx.x >> 6;
        float (*red)[64][15] = (float(*)[64][15])sh;

        float acc[15];
        #pragma unroll
        for (int i = 0; i < 15; i++) acc[i] = 0.f;

        for (int c = cg*64; c < cg*64 + 64; c++) {
            int hh = c >> 6;
            int m  = c & 63;
            float kv = K[(((bs*H_ + hh)*L_) + m*16 + gg)*D_ + q];
            #pragma unroll
            for (int nc = 0; nc < 5; nc++)
                #pragma unroll
                for (int t = 0; t < 3; t++)
                    acc[nc*3+t] += kv * __ldg(&wk[nc*1536 + c*3 + t]);
        }

        #pragma unroll
        for (int i = 0; i < 15; i++) red[cg][q][i] = acc[i];
        __syncthreads();
        if (cg == 0) {
            int ll2 = gg*64 + q;
            #pragma unroll
            for (int i = 0; i < 15; i++) {
                float s = 0.f;
                #pragma unroll
                for (int r = 0; r < 8; r++) s += red[r][q][i];
                g_G[(bs*15 + i)*L_ + ll2] = s;
            }
        }
    } else {
        int vb = blk - 128;
        int bh = vb >> 3, ch = vb & 7;
        const float* Vb = V + ((size_t)bh*L_ + ch*128)*D_;
        float (*t)[65] = (float(*)[65])sh;
        for (int i = threadIdx.x; i < 128*64/4; i += 512) {
            float4 v4 = ((const float4*)Vb)[i];
            int r = i >> 4, cl = (i & 15)*4;
            t[r][cl] = v4.x; t[r][cl+1] = v4.y; t[r][cl+2] = v4.z; t[r][cl+3] = v4.w;
        }
        __syncthreads();
        for (int i = threadIdx.x; i < 64*128; i += 512) {
            int d = i >> 7, key = i & 127;
            g_vh[((size_t)bh*64 + d)*1024 + ch*128 + key] = __float2half_rn(t[key][d]);
        }
    }
}

// ---------------- kernel 2: per-(bb,ll2) cluster math + loss partials --------
__global__ void k_small(const float* __restrict__ bk,
                        const float* __restrict__ wck, const float* __restrict__ bck,
                        const float* __restrict__ wcq, const float* __restrict__ bcq) {
    int idx = blockIdx.x*blockDim.x + threadIdx.x;
    int bb = idx >> 10, ll = idx & 1023;

    float ckp[5][5];
    #pragma unroll
    for (int j = 0; j < 5; j++)
        #pragma unroll
        for (int nc = 0; nc < 5; nc++) {
            float a = bk[nc];
            #pragma unroll
            for (int t = 0; t < 3; t++) {
                int jj = j + t - 1;
                if (jj >= 0 && jj < 5) {
                    int bs = bb + jj - 4;
                    if (bs >= 1) a += g_G[(bs*15 + nc*3 + t)*L_ + ll];
                }
            }
            ckp[j][nc] = fmaxf(a, 0.f);
        }

    float ck[5][5], cq[5][5];
    float lp_local = 0.f;
    #pragma unroll
    for (int j = 0; j < 5; j++) {
        float zk[5], zq[5];
        #pragma unroll
        for (int o = 0; o < 5; o++) {
            float sk = bck[o], sq = bcq[o];
            #pragma unroll
            for (int nc = 0; nc < 5; nc++) {
                sk += ckp[j][nc]*wck[o*5+nc];
                sq += ckp[j][nc]*wcq[o*5+nc];
            }
            zk[o] = sk; zq[o] = sq;
        }
        float mk = zk[0], mq = zq[0];
        #pragma unroll
        for (int o = 1; o < 5; o++) { mk = fmaxf(mk, zk[o]); mq = fmaxf(mq, zq[o]); }
        float sks = 0.f, sqs = 0.f;
        #pragma unroll
        for (int o = 0; o < 5; o++) {
            float ek = expf(zk[o]-mk), eq = expf(zq[o]-mq);
            ck[j][o] = ek; cq[j][o] = eq; sks += ek; sqs += eq;
        }
        float ik = 1.f/sks, iq = 1.f/sqs;
        #pragma unroll
        for (int o = 0; o < 5; o++) { ck[j][o] *= ik; cq[j][o] *= iq; }

        float mu = 0.f, x = 0.f;
        #pragma unroll
        for (int o = 0; o < 5; o++) { mu += cq[j][o]; x += ck[j][o]; }
        mu *= 0.2f; x *= 0.2f;
        float var = 0.f;
        #pragma unroll
        for (int o = 0; o < 5; o++) { float d = cq[j][o]-mu; var += d*d; }
        var *= 0.25f;
        float sd    = sqrtf(var);
        float sigma = logf(1.f + expf(sd));
        float z     = (x - mu)/sigma;
        lp_local += -0.5f*z*z - logf(sigma) - 0.91893853320467274f;
        g_mu[idx*5 + j] = mu;
    }

    #pragma unroll
    for (int p = 0; p < 5; p++) {
        float sc[5];
        #pragma unroll
        for (int j = 0; j < 5; j++) {
            if (j > p) { sc[j] = -1e9f; continue; }
            float d = 0.f;
            #pragma unroll
            for (int c = 0; c < 5; c++) d += cq[p][c]*ck[j][c];
            sc[j] = d*0.2f;
        }
        float mx = sc[0];
        #pragma unroll
        for (int j = 1; j < 5; j++) mx = fmaxf(mx, sc[j]);
        float se = 0.f, ew[5];
        #pragma unroll
        for (int j = 0; j < 5; j++) { ew[j] = expf(sc[j]-mx); se += ew[j]; }
        float inv = 1.f/se;
        #pragma unroll
        for (int c = 0; c < 5; c++) {
            float v = 0.f;
            #pragma unroll
            for (int j = 0; j < 5; j++) v += ew[j]*cq[j][c];
            g_q2[idx*25 + p*5 + c] = v*inv;
        }
    }

    #pragma unroll
    for (int off = 16; off; off >>= 1)
        lp_local += __shfl_down_sync(0xffffffff, lp_local, off);
    if ((threadIdx.x & 31) == 0) atomicAdd(&g_lp_sum, lp_local);
}

// ---------------- kernel 3 (MERGED): proj (blocks 0..255) + ce (256..295) ----
__global__ void __launch_bounds__(1024) k_proj(const float* __restrict__ wpb,
                                               const float* __restrict__ bpb) {
    extern __shared__ float smp[];
    int blk = blockIdx.x;

    if (blk >= 256) {
        // ---- CE: log_softmax of mu over l, one thread per ll ----
        int blk2 = blk - 256;
        int bb = blk2 / 5, j = blk2 % 5;
        const float* base = g_mu + (bb << 10)*5 + j;
        float* shc = smp;                 // 1024 floats of the dynamic smem
        int tid = threadIdx.x;
        float mv = base[tid*5];

        shc[tid] = mv; __syncthreads();
        for (int s = 512; s > 0; s >>= 1) {
            if (tid < s) shc[tid] = fmaxf(shc[tid], shc[tid+s]);
            __syncthreads();
        }
        float mx = shc[0]; __syncthreads();

        shc[tid] = expf(mv - mx); __syncthreads();
        for (int s = 512; s > 0; s >>= 1) {
            if (tid < s) shc[tid] += shc[tid+s];
            __syncthreads();
        }
        float lse = mx + logf(shc[0]); __syncthreads();

        shc[tid] = mv*(mv - lse); __syncthreads();
        for (int s = 512; s > 0; s >>= 1) {
            if (tid < s) shc[tid] += shc[tid+s];
            __syncthreads();
        }
        if (tid == 0) atomicAdd(&g_ce_sum, shc[0]);
        return;
    }

    // ---- proj: warp-cooperative fused conv_back + u2-sum ----
    float* q2s = smp;            // 1024 rows x 28
    float* wsh = smp + 28672;    // 512 rows x 16
    int qtr = blk & 3;
    int hh  = (blk >> 2) & 7;
    int bb  = blk >> 5;

    const float* q2b = g_q2 + (bb << 10)*25;
    for (int i = threadIdx.x; i < 25600; i += 1024) {
        int row = i / 25;
        int col = i - row*25;
        q2s[row*28 + col] = q2b[i];
    }
    for (int i = threadIdx.x; i < 512*16; i += 1024) {
        int c = i >> 4, e = i & 15;
        wsh[i] = (e < 15) ? __ldg(&wpb[c*15 + e]) : __ldg(&bpb[c]);
    }
    __syncthreads();

    int p0 = qtr*3277;
    int p1 = min(p0 + 3277, 13108);
    size_t obase = (size_t)(bb*8 + hh)*65536;
    int warp = threadIdx.x >> 5, lane = threadIdx.x & 31;

    for (int kb = p0 + warp*31; kb < p1; kb += 32*31) {
        int k = kb + lane;
        float acc[5] = {0.f, 0.f, 0.f, 0.f, 0.f};

        #pragma unroll
        for (int u2 = 0; u2 < 5; u2++) {
            int kw = min(kb + lane, 13107);
            int W  = (hh*5 + u2)*13107 + hh + kw;
            int c  = W >> 10, ll = W & 1023;

            const float4* qp = (const float4*)(q2s + ll*28);
            float4 q0 = qp[0], q1 = qp[1], q2v = qp[2],
                   q3 = qp[3], q4 = qp[4], q5 = qp[5];
            float q24 = q2s[ll*28 + 24];
            const float4* wp = (const float4*)(wsh + c*16);
            float4 w0 = wp[0], w1 = wp[1], w2 = wp[2], w3 = wp[3];

            float qr[25] = {q0.x,q0.y,q0.z,q0.w, q1.x,q1.y,q1.z,q1.w,
                            q2v.x,q2v.y,q2v.z,q2v.w, q3.x,q3.y,q3.z,q3.w,
                            q4.x,q4.y,q4.z,q4.w, q5.x,q5.y,q5.z,q5.w, q24};
            float wr[15] = {w0.x,w0.y,w0.z,w0.w, w1.x,w1.y,w1.z,w1.w,
                            w2.x,w2.y,w2.z,w2.w, w3.x,w3.y,w3.z};
            float bias = w3.w;

            float Dm[5][3];
            #pragma unroll
            for (int jj = 0; jj < 5; jj++)
                #pragma unroll
                for (int t = 0; t < 3; t++) {
                    float d = 0.f;
                    #pragma unroll
                    for (int nc = 0; nc < 5; nc++)
                        d += qr[jj*5 + nc]*wr[nc*3 + t];
                    Dm[jj][t] = d;
                }
            float y[5];
            #pragma unroll
            for (int j = 0; j < 5; j++) {
                float v = bias + Dm[j][1];
                if (j >= 1) v += Dm[j-1][0];
                if (j <= 3) v += Dm[j+1][2];
                y[j] = fmaxf(v, 0.f);
            }

            float ynx[5];
            #pragma unroll
            for (int j = 0; j < 5; j++)
                ynx[j] = __shfl_down_sync(0xffffffffu, y[j], 1);

            #pragma unroll
            for (int i = 0; i < 5; i++)
                acc[i] += (u2 + i < 5) ? y[u2 + i] : ynx[i - 5 + u2];
        }

        if (lane < 31 && k < p1) {
            int pos0 = k*5;
            int valid = min(5, 65536 - pos0);
            #pragma unroll
            for (int i = 0; i < 5; i++)
                if (i < valid) {
                    __half h = __float2half_rn(acc[i]);
                    g_kh[obase + pos0 + i] = h;
                    g_kl[obase + pos0 + i] = __float2half_rn(acc[i] - __half2float(h));
                }
        }
    }
}

// ---------------- kernel 4: flash attention (R13 structure) + loss block -----
__device__ __forceinline__ void mma16816(float d[4], const uint32_t a[4], const uint32_t b0, const uint32_t b1) {
    asm volatile("mma.sync.aligned.m16n8k16.row.col.f32.f16.f16.f32 "
                 "{%0,%1,%2,%3}, {%4,%5,%6,%7}, {%8,%9}, {%0,%1,%2,%3};\n"
                 : "+f"(d[0]), "+f"(d[1]), "+f"(d[2]), "+f"(d[3])
                 : "r"(a[0]), "r"(a[1]), "r"(a[2]), "r"(a[3]), "r"(b0), "r"(b1));
}
__device__ __forceinline__ void ldm4(uint32_t r[4], uint32_t addr) {
    asm volatile("ldmatrix.sync.aligned.m8n8.x4.shared.b16 {%0,%1,%2,%3}, [%4];\n"
                 : "=r"(r[0]), "=r"(r[1]), "=r"(r[2]), "=r"(r[3]) : "r"(addr));
}
__device__ __forceinline__ uint32_t packh(__half x, __half y) {
    __half2 h = __halves2half2(x, y);
    return *reinterpret_cast<uint32_t*>(&h);
}
__device__ __forceinline__ void split2(float2 f, uint32_t& hi, uint32_t& lo) {
    __half hx = __float2half_rn(f.x), hy = __float2half_rn(f.y);
    __half lx = __float2half_rn(f.x - __half2float(hx));
    __half ly = __float2half_rn(f.y - __half2float(hy));
    hi = packh(hx, hy); lo = packh(lx, ly);
}
__device__ __forceinline__ float ex2(float x) {
    float y; asm("ex2.approx.f32 %0, %1;" : "=f"(y) : "f"(x)); return y;
}
__device__ __forceinline__ void cpasync16(uint32_t smem_addr, const void* gptr) {
    asm volatile("cp.async.cg.shared.global [%0], [%1], 16;\n" :: "r"(smem_addr), "l"(gptr));
}

#define PADT 72
#define TILE_H (64*PADT)
#define STAGE_B (3*TILE_H*2)

__global__ void __launch_bounds__(256, 2) k_attn(const float* __restrict__ Q,
                                                 float* __restrict__ out) {
    extern __shared__ __half sm[];
    if (blockIdx.x >= 512) {          // loss block (inputs complete pre-launch)
        if (threadIdx.x == 0)
            out[B_*H_*L_*D_] = -(g_lp_sum / 40960.f) - (g_ce_sum / 40.f);
        return;
    }
    int bh = blockIdx.x >> 3, qt = blockIdx.x & 7;
    int tid = threadIdx.x, w = tid >> 5, lane = tid & 31;
    int g = lane >> 2, c4 = lane & 3;

    const __half* khg = g_kh + (size_t)bh*L_*D_;
    const __half* klg = g_kl + (size_t)bh*L_*D_;
    const __half* vhg = g_vh + (size_t)bh*D_*L_;

    const float LOG2E = 1.44269504088896340736f;
    uint32_t qfh[4][4], qfl[4][4];
    const float* Qb = Q + ((size_t)bh*L_ + qt*128 + w*16)*D_;
    #pragma unroll
    for (int kc = 0; kc < 4; kc++) {
        int col0 = kc*16 + 2*c4;
        float2 a0 = *(const float2*)(Qb + g*D_     + col0);
        float2 a1 = *(const float2*)(Qb + (g+8)*D_ + col0);
        float2 a2 = *(const float2*)(Qb + g*D_     + col0 + 8);
        float2 a3 = *(const float2*)(Qb + (g+8)*D_ + col0 + 8);
        a0.x *= LOG2E; a0.y *= LOG2E; a1.x *= LOG2E; a1.y *= LOG2E;
        a2.x *= LOG2E; a2.y *= LOG2E; a3.x *= LOG2E; a3.y *= LOG2E;
        split2(a0, qfh[kc][0], qfl[kc][0]);
        split2(a1, qfh[kc][1], qfl[kc][1]);
        split2(a2, qfh[kc][2], qfl[kc][2]);
        split2(a3, qfh[kc][3], qfl[kc][3]);
    }

    float o[8][4];
    #pragma unroll
    for (int i = 0; i < 8; i++)
        #pragma unroll
        for (int e = 0; e < 4; e++) o[i][e] = 0.f;
    float m0 = -1e30f, m1 = -1e30f, l0 = 0.f, l1 = 0.f;

    uint32_t smbase = (uint32_t)__cvta_generic_to_shared(sm);
    int lrow = ((lane >> 4) << 3) + (lane & 7);
    uint32_t lsel = ((lane >> 3) & 1) << 3;
    uint32_t laneoff = (uint32_t)(lrow*PADT + lsel)*2;

    auto stage = [&](int kt, int s) {
        uint32_t b = smbase + (uint32_t)s*STAGE_B;
        #pragma unroll
        for (int i = tid; i < 1536; i += 256) {
            int arr = i >> 9, j = i & 511;
            int r = j >> 3, ch = j & 7;
            const __half* src;
            if (arr == 0)      src = khg + kt*4096 + r*64 + ch*8;
            else if (arr == 1) src = klg + kt*4096 + r*64 + ch*8;
            else               src = vhg + r*1024 + kt*64 + ch*8;
            cpasync16(b + (uint32_t)arr*(TILE_H*2) + (uint32_t)(r*PADT + ch*8)*2, src);
        }
    };

    stage(0, 0);
    asm volatile("cp.async.commit_group;\n");
    stage(1, 1);
    asm volatile("cp.async.commit_group;\n");

    int bufA = 0, bufB = 1, bufC = 2;
    for (int kt = 0; kt < 16; kt++) {
        asm volatile("cp.async.wait_group 1;\n");
        __syncthreads();

        uint32_t kh_b = smbase + (uint32_t)bufA*STAGE_B + laneoff;
        uint32_t kl_b = kh_b + TILE_H*2;
        uint32_t vh_b = kl_b + TILE_H*2;

        #pragma unroll
        for (int hf = 0; hf < 2; hf++) {
            float s[4][4];
            #pragma unroll
            for (int nt = 0; nt < 4; nt++)
                #pragma unroll
                for (int e = 0; e < 4; e++) s[nt][e] = 0.f;

            #pragma unroll
            for (int kc = 0; kc < 4; kc++) {
                #pragma unroll
                for (int np = 0; np < 2; np++) {
                    uint32_t off = (uint32_t)((hf*32 + np*16)*PADT + kc*16)*2;
                    uint32_t bhm[4], blm[4];
                    ldm4(bhm, kh_b + off);
                    ldm4(blm, kl_b + off);
                    mma16816(s[np*2],   qfh[kc], bhm[0], bhm[1]);
                    mma16816(s[np*2],   qfl[kc], bhm[0], bhm[1]);
                    mma16816(s[np*2],   qfh[kc], blm[0], blm[1]);
                    mma16816(s[np*2+1], qfh[kc], bhm[2], bhm[3]);
                    mma16816(s[np*2+1], qfl[kc], bhm[2], bhm[3]);
                    mma16816(s[np*2+1], qfh[kc], blm[2], blm[3]);
                }
            }

            float mt0 = s[0][0], mt1 = s[0][2];
            #pragma unroll
            for (int nt = 0; nt < 4; nt++) {
                mt0 = fmaxf(mt0, fmaxf(s[nt][0], s[nt][1]));
                mt1 = fmaxf(mt1, fmaxf(s[nt][2], s[nt][3]));
            }
            mt0 = fmaxf(mt0, __shfl_xor_sync(0xffffffff, mt0, 1));
            mt0 = fmaxf(mt0, __shfl_xor_sync(0xffffffff, mt0, 2));
            mt1 = fmaxf(mt1, __shfl_xor_sync(0xffffffff, mt1, 1));
            mt1 = fmaxf(mt1, __shfl_xor_sync(0xffffffff, mt1, 2));
            float m0n = fmaxf(m0, mt0), m1n = fmaxf(m1, mt1);
            bool need = (m0n > m0) || (m1n > m1);
            if (__ballot_sync(0xffffffffu, need)) {
                float sc0 = ex2(m0 - m0n), sc1 = ex2(m1 - m1n);
                l0 *= sc0; l1 *= sc1;
                #pragma unroll
                for (int i = 0; i < 8; i++) {
                    o[i][0] *= sc0; o[i][1] *= sc0;
                    o[i][2] *= sc1; o[i][3] *= sc1;
                }
            }
            m0 = m0n; m1 = m1n;

            uint32_t PH[4][2];
            #pragma unroll
            for (int nt = 0; nt < 4; nt++) {
                float p0 = ex2(s[nt][0] - m0), p1 = ex2(s[nt][1] - m0);
                float p2 = ex2(s[nt][2] - m1), p3 = ex2(s[nt][3] - m1);
                l0 += p0 + p1; l1 += p2 + p3;
                PH[nt][0] = packh(__float2half_rn(p0), __float2half_rn(p1));
                PH[nt][1] = packh(__float2half_rn(p2), __float2half_rn(p3));
            }

            #pragma unroll
            for (int kc2 = 0; kc2 < 2; kc2++) {
                uint32_t Ah[4] = {PH[2*kc2][0], PH[2*kc2][1], PH[2*kc2+1][0], PH[2*kc2+1][1]};
                #pragma unroll
                for (int np = 0; np < 4; np++) {
                    uint32_t off = (uint32_t)(np*16*PADT + hf*32 + kc2*16)*2;
                    uint32_t bvm[4];
                    ldm4(bvm, vh_b + off);
                    mma16816(o[np*2],   Ah, bvm[0], bvm[1]);
                    mma16816(o[np*2+1], Ah, bvm[2], bvm[3]);
                }
            }
        }

        if (kt < 14) stage(kt+2, bufC);
        asm volatile("cp.async.commit_group;\n");
        int tmp = bufA; bufA = bufB; bufB = bufC; bufC = tmp;
    }

    l0 += __shfl_xor_sync(0xffffffff, l0, 1);
    l0 += __shfl_xor_sync(0xffffffff, l0, 2);
    l1 += __shfl_xor_sync(0xffffffff, l1, 1);
    l1 += __shfl_xor_sync(0xffffffff, l1, 2);
    float inv0 = 1.f/l0, inv1 = 1.f/l1;

    float* Ob = out + ((size_t)bh*L_ + qt*128 + w*16)*D_;
    #pragma unroll
    for (int nt = 0; nt < 8; nt++) {
        int col = nt*8 + 2*c4;
        *(float2*)(Ob + g*D_     + col) = make_float2(o[nt][0]*inv0, o[nt][1]*inv0);
        *(float2*)(Ob + (g+8)*D_ + col) = make_float2(o[nt][2]*inv1, o[nt][3]*inv1);
    }
}

// ---------------- launcher ---------------------------------------------------
extern "C" void kernel_launch(void* const* d_in, const int* in_sizes, int n_in,
                              void* d_out, int out_size) {
    const float* Q   = (const float*)d_in[0];
    const float* K   = (const float*)d_in[1];
    const float* V   = (const float*)d_in[2];
    const float* wpk = (const float*)d_in[3];
    const float* bpk = (const float*)d_in[4];
    const float* wpb = (const float*)d_in[5];
    const float* bpb = (const float*)d_in[6];
    const float* wck = (const float*)d_in[7];
    const float* bck = (const float*)d_in[8];
    const float* wcq = (const float*)d_in[9];
    const float* bcq = (const float*)d_in[10];
    float* out = (float*)d_out;

    const int ATTN_SMEM = 3*STAGE_B;                 // 82944 B
    const int PROJ_SMEM = (1024*28 + 512*16)*4;      // 147456 B
    cudaFuncSetAttribute(k_attn, cudaFuncAttributeMaxDynamicSharedMemorySize, ATTN_SMEM);
    cudaFuncSetAttribute(k_proj, cudaFuncAttributeMaxDynamicSharedMemorySize, PROJ_SMEM);

    const int N = B_*H_*L_*D_;
    int loss_blocks = (out_size > N) ? 1 : 0;

    k_prep<<<128 + B_*H_*8, 512>>>(K, wpk, V);                // 1: gmat + vprep
    k_small<<<(B_*L_)/64, 64>>>(bpk, wck, bck, wcq, bcq);     // 2
    k_proj<<<256 + B_*NC_, 1024, PROJ_SMEM>>>(wpb, bpb);      // 3: proj + ce (296 blocks = 2 waves)
    k_attn<<<B_*H_*8 + loss_blocks, 256, ATTN_SMEM>>>(Q, out);// 4: attn + loss
}